// round 14
// baseline (speedup 1.0000x reference)
#include <cuda_runtime.h>
#include <cuda_fp16.h>
#include <cstdint>

#define B_ 4
#define S_ 2048
#define E_ 1024
#define H_ 16
#define D_ 64
#define L_ 4
#define M_ (B_*S_)          // 8192 rows
#define PW_ (S_/32)         // 64 mask words per row
#define SCALE_ 0.03125f     // E^-0.5
#define EPS_ 1e-5f

// ---------------- scratch (__device__ globals: allocation-free rule) -------
__device__ float g_x[M_*E_];
__device__ float g_proj[M_*E_];
__device__ unsigned g_pmask[B_*S_*PW_];
__device__ __half g_xh[M_*E_],  g_xl[M_*E_];
__device__ __half g_qh[M_*E_];
__device__ __half g_kh[L_*M_*E_], g_kl[L_*M_*E_];   // all layers (value is layer-invariant)
__device__ __half g_vh[L_*M_*E_], g_vl[L_*M_*E_];
__device__ __half g_ath[M_*E_], g_atl[M_*E_];
__device__ __half g_vih[M_*E_], g_vil[M_*E_];
__device__ __half g_wh[L_*4*E_*E_];   // weights [N][K] (transposed), fp16

// ============================ portable PTX helpers ==========================
__device__ __forceinline__ uint32_t smem_to_u32(const void* p) {
    uint32_t a;
    asm("{ .reg .u64 t; cvta.to.shared.u64 t, %1; cvt.u32.u64 %0, t; }"
        : "=r"(a) : "l"(p));
    return a;
}
#define SMEM_SWIZZLE_128B(o) ((o) ^ (((o) >> 3) & 0x70))

__device__ __forceinline__ void cp16(uint32_t dst, const void* src) {
    asm volatile("cp.async.cg.shared.global [%0], [%1], 16;" :: "r"(dst), "l"(src) : "memory");
}
#define CP_COMMIT() asm volatile("cp.async.commit_group;" ::: "memory")
#define CP_WAIT0()  asm volatile("cp.async.wait_group 0;" ::: "memory")
#define CP_WAIT1()  asm volatile("cp.async.wait_group 1;" ::: "memory")

__device__ __forceinline__ void ldsm4(uint32_t* r, uint32_t a) {
    asm volatile("ldmatrix.sync.aligned.m8n8.x4.shared.b16 {%0,%1,%2,%3}, [%4];"
        : "=r"(r[0]), "=r"(r[1]), "=r"(r[2]), "=r"(r[3]) : "r"(a));
}
__device__ __forceinline__ void ldsm4t(uint32_t* r, uint32_t a) {
    asm volatile("ldmatrix.sync.aligned.m8n8.x4.trans.shared.b16 {%0,%1,%2,%3}, [%4];"
        : "=r"(r[0]), "=r"(r[1]), "=r"(r[2]), "=r"(r[3]) : "r"(a));
}
// D += A(16x16) * B(16x8), fp16 in, fp32 accum
__device__ __forceinline__ void mma_f16(float* c, const uint32_t* a, const uint32_t* b) {
    asm volatile("mma.sync.aligned.m16n8k16.row.col.f32.f16.f16.f32 "
        "{%0,%1,%2,%3}, {%4,%5,%6,%7}, {%8,%9}, {%0,%1,%2,%3};"
        : "+f"(c[0]), "+f"(c[1]), "+f"(c[2]), "+f"(c[3])
        : "r"(a[0]), "r"(a[1]), "r"(a[2]), "r"(a[3]), "r"(b[0]), "r"(b[1]));
}
__device__ __forceinline__ void split2h(float v0, float v1, uint32_t& hi, uint32_t& lo) {
    __half2 h = __floats2half2_rn(v0, v1);
    float2 hf = __half22float2(h);
    __half2 l = __floats2half2_rn(v0 - hf.x, v1 - hf.y);
    hi = *(uint32_t*)&h; lo = *(uint32_t*)&l;
}
__device__ __forceinline__ uint32_t pack_h2(float v0, float v1) {
    __half2 h = __floats2half2_rn(v0, v1);
    return *(uint32_t*)&h;
}

// ---------------------------------------------------------------------------
__global__ void pack_mask_kernel(const int* __restrict__ mask) {
    unsigned i = blockIdx.x * 256u + threadIdx.x;
    unsigned word = __ballot_sync(0xffffffffu, mask[i] == 1);
    if ((threadIdx.x & 31) == 0) g_pmask[i >> 5] = word;
}

__global__ void split_act_kernel(const float* __restrict__ src,
                                 __half* __restrict__ hi,
                                 __half* __restrict__ lo) {
    size_t i = (size_t)blockIdx.x * 256 + threadIdx.x;
    float4 v = ((const float4*)src)[i];
    uint32_t h01, l01, h23, l23;
    split2h(v.x, v.y, h01, l01);
    split2h(v.z, v.w, h23, l23);
    ((uint2*)hi)[i] = make_uint2(h01, h23);
    ((uint2*)lo)[i] = make_uint2(l01, l23);
}

// All 4 weight matrices, all layers, one launch: out[n][k] = fp16(W[k][n]).
__global__ void split_wT_all_kernel(const float* __restrict__ Wq,
                                    const float* __restrict__ Wk,
                                    const float* __restrict__ Wv,
                                    const float* __restrict__ Wo,
                                    __half* __restrict__ hibase) {
    __shared__ float t[32][33];
    int layer = blockIdx.z >> 2, slot = blockIdx.z & 3;
    const float* Wb = (slot == 0) ? Wq : (slot == 1) ? Wk : (slot == 2) ? Wv : Wo;
    const float* W = Wb + (size_t)layer * E_ * E_;
    __half* hi = hibase + ((size_t)blockIdx.z << 20);
    int bn = blockIdx.x * 32, bk = blockIdx.y * 32;
    int tx = threadIdx.x, ty = threadIdx.y;
    #pragma unroll
    for (int i = 0; i < 32; i += 8)
        t[ty + i][tx] = W[(size_t)(bk + ty + i) * E_ + bn + tx];
    __syncthreads();
    #pragma unroll
    for (int i = 0; i < 32; i += 8)
        hi[(size_t)(bn + ty + i) * E_ + bk + tx] = __float2half(t[tx][ty + i]);
}

// ---------------------------------------------------------------------------
// fp16x2 MMA GEMM: C = (Ah+Al) @ Wh^T + bias. CTA tile 256x128, 512 threads,
// warp tile 64x32, K-chunk 64, double-buffered cp.async.
// MODE 0: fp32 out. MODE 2: fp16 hi only.
// MODE 3: mega K/V — bn decodes (layer, K-or-V, col-block); fp16 hi/lo out.
// ---------------------------------------------------------------------------
#define GS_AL 32768
#define GS_W  65536
#define GSTAGE 81920

__device__ __forceinline__ void gemm_load_stage(uint32_t base,
        const char* gA_h, const char* gA_l, const char* gW,
        int kc, int tid) {
    size_t co = (size_t)kc * 128;
    #pragma unroll
    for (int i = 0; i < 4; i++) {           // A: 256 rows x 8 seg, hi+lo
        int idx = tid + i * 512;
        int r = idx >> 3, sg = idx & 7;
        uint32_t so = SMEM_SWIZZLE_128B((uint32_t)(r * 128 + sg * 16));
        size_t go = (size_t)r * 2048 + co + sg * 16;
        cp16(base + so, gA_h + go);
        cp16(base + GS_AL + so, gA_l + go);
    }
    #pragma unroll
    for (int i = 0; i < 2; i++) {           // W: 128 rows x 8 seg
        int idx = tid + i * 512;
        int r = idx >> 3, sg = idx & 7;
        uint32_t so = SMEM_SWIZZLE_128B((uint32_t)(r * 128 + sg * 16));
        cp16(base + GS_W + so, gW + (size_t)r * 2048 + co + sg * 16);
    }
}

template<int MODE>
__global__ __launch_bounds__(512, 1)
void gemm_mma(const __half* __restrict__ Ah, const __half* __restrict__ Al,
              const __half* __restrict__ Wh,
              const float* __restrict__ bias, const float* __restrict__ bias2,
              float* __restrict__ C,
              __half* __restrict__ Hh, __half* __restrict__ Hl,
              __half* __restrict__ Hh2, __half* __restrict__ Hl2) {
    extern __shared__ char smem[];
    const uint32_t sb = smem_to_u32(smem);
    const int tid = threadIdx.x, lane = tid & 31, w = tid >> 5;
    const int bm = blockIdx.y, bn = blockIdx.x;
    const int m0 = (w & 3) * 64, n0 = (w >> 2) * 32;

    const char* gA_h = (const char*)(Ah + (size_t)bm * 256 * E_);
    const char* gA_l = (const char*)(Al + (size_t)bm * 256 * E_);
    const char* gW;
    const float* bias_sel = bias;
    __half *HhU = Hh, *HlU = Hl;
    int colbase;
    if (MODE == 3) {
        int layer = bn >> 4, sub = bn & 15;
        int slot = sub >> 3, wcol = sub & 7;
        gW = (const char*)(Wh + (((size_t)(layer * 4 + 1 + slot)) << 20)
                              + (size_t)wcol * 128 * E_);
        bias_sel = (slot ? bias2 : bias) + layer * E_;
        HhU = (slot ? Hh2 : Hh) + (size_t)layer * ((size_t)M_ * E_);
        HlU = (slot ? Hl2 : Hl) + (size_t)layer * ((size_t)M_ * E_);
        colbase = wcol * 128;
    } else {
        gW = (const char*)(Wh + (size_t)bn * 128 * E_);
        colbase = bn * 128;
    }

    const int arow = m0 + (lane & 15);
    const uint32_t a_kb = (uint32_t)((lane >> 4) * 16);
    const uint32_t axor = (uint32_t)((arow & 7) << 4);
    const int brow = n0 + (lane & 7) + ((lane >> 4) << 3);
    const uint32_t b_kb = (uint32_t)(((lane >> 3) & 1) * 16);
    const uint32_t bxor = (uint32_t)((brow & 7) << 4);

    float c[4][4][4];
    #pragma unroll
    for (int i = 0; i < 4; i++)
        #pragma unroll
        for (int j = 0; j < 4; j++)
            #pragma unroll
            for (int q = 0; q < 4; q++) c[i][j][q] = 0.f;

    gemm_load_stage(sb, gA_h, gA_l, gW, 0, tid);
    CP_COMMIT();

    for (int kc = 0; kc < 16; kc++) {
        uint32_t stg = sb + (uint32_t)((kc & 1) * GSTAGE);
        CP_WAIT0();
        __syncthreads();            // stage kc visible; all warps done with kc-1
        if (kc + 1 < 16) {
            gemm_load_stage(sb + (uint32_t)(((kc + 1) & 1) * GSTAGE),
                            gA_h, gA_l, gW, kc + 1, tid);
            CP_COMMIT();
        }
        #pragma unroll
        for (int kk = 0; kk < 4; kk++) {
            uint32_t ah[4][4], al[4][4], bh[2][4];
            #pragma unroll
            for (int mt = 0; mt < 4; mt++) {
                uint32_t ra = stg + (uint32_t)((arow + mt * 16) * 128)
                                  + (((uint32_t)(kk * 32) + a_kb) ^ axor);
                ldsm4(ah[mt], ra);
                ldsm4(al[mt], ra + GS_AL);
            }
            #pragma unroll
            for (int p = 0; p < 2; p++) {
                uint32_t rb = stg + GS_W + (uint32_t)((brow + p * 16) * 128)
                                  + (((uint32_t)(kk * 32) + b_kb) ^ bxor);
                ldsm4(bh[p], rb);
            }
            #pragma unroll
            for (int mt = 0; mt < 4; mt++)
                #pragma unroll
                for (int p = 0; p < 2; p++)
                    #pragma unroll
                    for (int t = 0; t < 2; t++)
                        mma_f16(c[mt][p*2+t], ah[mt], &bh[p][t*2]);
            #pragma unroll
            for (int mt = 0; mt < 4; mt++)
                #pragma unroll
                for (int p = 0; p < 2; p++)
                    #pragma unroll
                    for (int t = 0; t < 2; t++)
                        mma_f16(c[mt][p*2+t], al[mt], &bh[p][t*2]);
        }
    }

    // epilogue
    const int g = lane >> 2, tg = lane & 3;
    #pragma unroll
    for (int nt = 0; nt < 4; nt++) {
        int col = colbase + n0 + nt * 8 + 2 * tg;
        float b0 = bias_sel[col], b1 = bias_sel[col + 1];
        #pragma unroll
        for (int mt = 0; mt < 4; mt++) {
            int row = bm * 256 + m0 + mt * 16 + g;
            float v0 = c[mt][nt][0] + b0, v1 = c[mt][nt][1] + b1;
            float v2 = c[mt][nt][2] + b0, v3 = c[mt][nt][3] + b1;
            size_t i0 = (size_t)row * E_ + col;
            size_t i1 = i0 + (size_t)8 * E_;
            if (MODE == 3) {
                uint32_t h01, l01, h23, l23;
                split2h(v0, v1, h01, l01);
                split2h(v2, v3, h23, l23);
                *(uint32_t*)(HhU + i0) = h01; *(uint32_t*)(HlU + i0) = l01;
                *(uint32_t*)(HhU + i1) = h23; *(uint32_t*)(HlU + i1) = l23;
            } else if (MODE == 2) {
                *(uint32_t*)(HhU + i0) = pack_h2(v0, v1);
                *(uint32_t*)(HhU + i1) = pack_h2(v2, v3);
            } else {
                *(float2*)(C + i0) = make_float2(v0, v1);
                *(float2*)(C + i1) = make_float2(v2, v3);
            }
        }
    }
}

// ---------------------------------------------------------------------------
// Fused ReLU attention, fp16 2-term (Qh@(Kh+Kl), Sh@(Vh+Vl)), all f32 accum.
// 512 threads; warp (qg 0-7, kvh 0-1): 16q x 64kv per chunk; Q resident.
// smem: Qh 16K | 3 x (Kh|Kl|Vh|Vl 16K each) = 208K
// ---------------------------------------------------------------------------
#define AKV(s) (16384 + (s) * 65536)
#define AKL 16384
#define AVH 32768
#define SMEM_ATTN 212992

__device__ __forceinline__ void attn_load_kv(uint32_t base,
        const char* gK_h, const char* gK_l, const char* gV_h, const char* gV_l,
        int kc, int tid) {
    #pragma unroll
    for (int i = 0; i < 2; i++) {
        int idx = tid + i * 512;
        int r = idx >> 3, sg = idx & 7;
        uint32_t so = SMEM_SWIZZLE_128B((uint32_t)(r * 128 + sg * 16));
        size_t go = (size_t)(kc * 128 + r) * 2048 + sg * 16;
        cp16(base + so,         gK_h + go);
        cp16(base + AKL + so,   gK_l + go);
        cp16(base + AVH + so,   gV_h + go);
        cp16(base + 49152 + so, gV_l + go);
    }
}

__global__ __launch_bounds__(512, 1)
void attn_mma(const __half* __restrict__ qh,
              const __half* __restrict__ kh, const __half* __restrict__ kl,
              const __half* __restrict__ vh, const __half* __restrict__ vl,
              __half* __restrict__ oh, __half* __restrict__ ol) {
    extern __shared__ char smem[];
    const uint32_t sb = smem_to_u32(smem);
    const int tid = threadIdx.x, lane = tid & 31, w = tid >> 5;
    const int qg = w & 7, kvh = w >> 3;
    const int qt = blockIdx.x, h = blockIdx.y, b = blockIdx.z;
    const int q0 = qt * 128;
    const int g = lane >> 2, tg = lane & 3;

    const size_t hb = ((size_t)b * S_) * E_ + h * D_;
    const char* gQ_h = (const char*)(qh + hb);
    const char* gK_h = (const char*)(kh + hb);
    const char* gK_l = (const char*)(kl + hb);
    const char* gV_h = (const char*)(vh + hb);
    const char* gV_l = (const char*)(vl + hb);
    const unsigned* pm = g_pmask + (size_t)b * S_ * PW_;

    // prologue: group0 = Q + KV0, group1 = KV1
    #pragma unroll
    for (int i = 0; i < 2; i++) {
        int idx = tid + i * 512;
        int r = idx >> 3, sg = idx & 7;
        uint32_t so = SMEM_SWIZZLE_128B((uint32_t)(r * 128 + sg * 16));
        cp16(sb + so, gQ_h + (size_t)(q0 + r) * 2048 + sg * 16);
    }
    attn_load_kv(sb + AKV(0), gK_h, gK_l, gV_h, gV_l, 0, tid);
    CP_COMMIT();
    attn_load_kv(sb + AKV(1), gK_h, gK_l, gV_h, gV_l, 1, tid);
    CP_COMMIT();

    // fragment addressing
    const int arow = qg * 16 + (lane & 15);
    const uint32_t a_kb = (uint32_t)((lane >> 4) * 16);
    const uint32_t lxor = (uint32_t)((lane & 7) << 4);
    const int brow = kvh * 64 + (lane & 7) + ((lane >> 4) << 3);   // + p*16
    const uint32_t b_kb = (uint32_t)(((lane >> 3) & 1) * 16);
    const int vrow = kvh * 64 + (lane & 15);            // + j*16
    const uint32_t vdb = (uint32_t)((lane >> 4) * 16);
    const int r0 = q0 + qg * 16 + g;                    // thread's q rows: r0, r0+8

    uint32_t qfh[4][4];                                 // Q fragments, resident
    float c2[8][4];                                     // O partial (16q x 64d)
    #pragma unroll
    for (int j = 0; j < 8; j++)
        #pragma unroll
        for (int q = 0; q < 4; q++) c2[j][q] = 0.f;

    for (int kc = 0; kc < 16; kc++) {
        uint32_t kv = sb + AKV(kc % 3);
        if (kc < 15) CP_WAIT1(); else CP_WAIT0();
        __syncthreads();            // stage kc visible; all warps done with kc-1
        if (kc + 2 < 16) {
            attn_load_kv(sb + AKV((kc + 2) % 3), gK_h, gK_l, gV_h, gV_l, kc + 2, tid);
            CP_COMMIT();
        }
        if (kc == 0) {              // Q fragments (arrived with group0)
            #pragma unroll
            for (int kk = 0; kk < 4; kk++) {
                uint32_t ra = sb + (uint32_t)(arow * 128)
                                 + (((uint32_t)(kk * 32) + a_kb) ^ lxor);
                ldsm4(qfh[kk], ra);
            }
        }

        // ---- stage 1: S(16q x 64kv) = Qh @ (Kh + Kl)^T ----
        float c1[8][4];
        #pragma unroll
        for (int j = 0; j < 8; j++)
            #pragma unroll
            for (int q = 0; q < 4; q++) c1[j][q] = 0.f;
        #pragma unroll
        for (int kk = 0; kk < 4; kk++) {
            #pragma unroll
            for (int p = 0; p < 4; p++) {
                uint32_t khf[4], klf[4];
                uint32_t rb = kv + (uint32_t)((brow + p * 16) * 128)
                                 + (((uint32_t)(kk * 32) + b_kb) ^ lxor);
                ldsm4(khf, rb);
                ldsm4(klf, rb + AKL);
                #pragma unroll
                for (int t = 0; t < 2; t++)
                    mma_f16(c1[p*2+t], qfh[kk], &khf[t*2]);
                #pragma unroll
                for (int t = 0; t < 2; t++)
                    mma_f16(c1[p*2+t], qfh[kk], &klf[t*2]);
            }
        }

        // ---- mask + relu + scale (registers) ----
        {
            size_t mb = (size_t)r0 * PW_ + kc * 4 + kvh * 2;
            unsigned m0a = pm[mb],         m0b = pm[mb + 1];
            unsigned m1a = pm[mb + PW_*8], m1b = pm[mb + PW_*8 + 1];
            #pragma unroll
            for (int nt = 0; nt < 8; nt++) {
                int col = nt * 8 + 2 * tg;
                int bit = col & 31;
                unsigned w0 = (col < 32) ? m0a : m0b;
                unsigned w1 = (col < 32) ? m1a : m1b;
                c1[nt][0] = ((w0 >> bit) & 1u)       ? 0.f : fmaxf(c1[nt][0] * SCALE_, 0.f);
                c1[nt][1] = ((w0 >> (bit + 1)) & 1u) ? 0.f : fmaxf(c1[nt][1] * SCALE_, 0.f);
                c1[nt][2] = ((w1 >> bit) & 1u)       ? 0.f : fmaxf(c1[nt][2] * SCALE_, 0.f);
                c1[nt][3] = ((w1 >> (bit + 1)) & 1u) ? 0.f : fmaxf(c1[nt][3] * SCALE_, 0.f);
            }
        }

        // ---- stage 2: O += Sh @ (Vh + Vl) ----
        #pragma unroll
        for (int j = 0; j < 4; j++) {
            uint32_t sh[4];
            sh[0] = pack_h2(c1[2*j][0],   c1[2*j][1]);
            sh[1] = pack_h2(c1[2*j][2],   c1[2*j][3]);
            sh[2] = pack_h2(c1[2*j+1][0], c1[2*j+1][1]);
            sh[3] = pack_h2(c1[2*j+1][2], c1[2*j+1][3]);
            #pragma unroll
            for (int p = 0; p < 4; p++) {
                uint32_t vhf[4], vlf[4];
                uint32_t off = (uint32_t)((vrow + j * 16) * 128) + (uint32_t)(p * 32) + vdb;
                uint32_t rb = kv + AVH + SMEM_SWIZZLE_128B(off);
                ldsm4t(vhf, rb);
                ldsm4t(vlf, rb + AKL);
                #pragma unroll
                for (int t = 0; t < 2; t++)
                    mma_f16(c2[p*2+t], sh, &vhf[t*2]);
                #pragma unroll
                for (int t = 0; t < 2; t++)
                    mma_f16(c2[p*2+t], sh, &vlf[t*2]);
            }
        }
    }

    // ---- cross-warp O reduction over kvh, then epilogue ----
    __syncthreads();                       // all reads of KV buffers done
    float* redp = (float*)(smem + 16384 + qg * 4096);   // 16x64 fp32 per q-group
    if (kvh == 1) {
        #pragma unroll
        for (int nt = 0; nt < 8; nt++) {
            int cidx = nt * 8 + 2 * tg;
            *(float2*)(redp + g * 64 + cidx) = make_float2(c2[nt][0], c2[nt][1]);
            *(float2*)(redp + (g + 8) * 64 + cidx) = make_float2(c2[nt][2], c2[nt][3]);
        }
    }
    __syncthreads();
    if (kvh == 0) {
        #pragma unroll
        for (int nt = 0; nt < 8; nt++) {
            int cidx = nt * 8 + 2 * tg;
            float2 p0 = *(float2*)(redp + g * 64 + cidx);
            float2 p1 = *(float2*)(redp + (g + 8) * 64 + cidx);
            float v0 = c2[nt][0] + p0.x, v1 = c2[nt][1] + p0.y;
            float v2 = c2[nt][2] + p1.x, v3 = c2[nt][3] + p1.y;
            size_t i0 = ((size_t)b * S_ + r0) * E_ + h * D_ + cidx;
            size_t i1 = i0 + (size_t)8 * E_;
            uint32_t h01, l01, h23, l23;
            split2h(v0, v1, h01, l01);
            split2h(v2, v3, h23, l23);
            *(uint32_t*)(oh + i0) = h01; *(uint32_t*)(ol + i0) = l01;
            *(uint32_t*)(oh + i1) = h23; *(uint32_t*)(ol + i1) = l23;
        }
    }
}

// ---------------------------------------------------------------------------
// out = LayerNorm(a + res)*gamma + beta ; also writes fp16 hi/lo of out
// ---------------------------------------------------------------------------
__global__ __launch_bounds__(256)
void add_ln_kernel(const float* __restrict__ a, const float* __restrict__ res,
                   const float* __restrict__ gamma, const float* __restrict__ beta,
                   float* __restrict__ out,
                   __half* __restrict__ oh, __half* __restrict__ ol) {
    __shared__ float red[8];
    __shared__ float bcast;
    const int row = blockIdx.x, tid = threadIdx.x;
    const int lane = tid & 31, wid = tid >> 5;
    const float* ap = a + (size_t)row * E_;
    const float* xp = res + (size_t)row * E_;
    float4 va = *(const float4*)(ap + tid * 4);
    float4 vx = *(const float4*)(xp + tid * 4);
    float v0 = va.x + vx.x, v1 = va.y + vx.y, v2 = va.z + vx.z, v3 = va.w + vx.w;
    float s = v0 + v1 + v2 + v3;
    #pragma unroll
    for (int off = 16; off > 0; off >>= 1) s += __shfl_xor_sync(~0u, s, off);
    if (lane == 0) red[wid] = s;
    __syncthreads();
    if (tid == 0) {
        float t = 0;
        #pragma unroll
        for (int i = 0; i < 8; i++) t += red[i];
        bcast = t;
    }
    __syncthreads();
    float mean = bcast * (1.0f / E_);
    float d0 = v0 - mean, d1 = v1 - mean, d2 = v2 - mean, d3 = v3 - mean;
    float vs = d0*d0 + d1*d1 + d2*d2 + d3*d3;
    #pragma unroll
    for (int off = 16; off > 0; off >>= 1) vs += __shfl_xor_sync(~0u, vs, off);
    __syncthreads();
    if (lane == 0) red[wid] = vs;
    __syncthreads();
    if (tid == 0) {
        float t = 0;
        #pragma unroll
        for (int i = 0; i < 8; i++) t += red[i];
        bcast = t;
    }
    __syncthreads();
    float inv = rsqrtf(bcast * (1.0f / E_) + EPS_);
    float4 gq = *(const float4*)(gamma + tid * 4);
    float4 bt = *(const float4*)(beta + tid * 4);
    float o0 = d0*inv*gq.x + bt.x, o1 = d1*inv*gq.y + bt.y;
    float o2 = d2*inv*gq.z + bt.z, o3 = d3*inv*gq.w + bt.w;
    *(float4*)(out + (size_t)row * E_ + tid * 4) = make_float4(o0, o1, o2, o3);
    uint32_t h01, l01, h23, l23;
    split2h(o0, o1, h01, l01);
    split2h(o2, o3, h23, l23);
    size_t i0 = (size_t)row * E_ + tid * 4;
    *(uint2*)(oh + i0) = make_uint2(h01, h23);
    *(uint2*)(ol + i0) = make_uint2(l01, l23);
}

// ---------------------------------------------------------------------------
extern "C" void kernel_launch(void* const* d_in, const int* in_sizes, int n_in,
                              void* d_out, int out_size) {
    const float* query = (const float*)d_in[0];
    const float* value = (const float*)d_in[1];
    const int*   mask  = (const int*)d_in[2];
    const float* Wq = (const float*)d_in[3];
    const float* Wk = (const float*)d_in[4];
    const float* Wv = (const float*)d_in[5];
    const float* Wo = (const float*)d_in[6];
    const float* bq = (const float*)d_in[7];
    const float* bk = (const float*)d_in[8];
    const float* bv = (const float*)d_in[9];
    const float* bo = (const float*)d_in[10];
    const float* gamma = (const float*)d_in[11];
    const float* beta  = (const float*)d_in[12];
    float* out = (float*)d_out;

    float *x, *proj;
    cudaGetSymbolAddress((void**)&x,    g_x);
    cudaGetSymbolAddress((void**)&proj, g_proj);
    __half *xh, *xl, *ath, *atl, *vih, *vil, *wh;
    __half *qh, *kh, *kl, *vh, *vl;
    cudaGetSymbolAddress((void**)&xh, g_xh);   cudaGetSymbolAddress((void**)&xl, g_xl);
    cudaGetSymbolAddress((void**)&qh, g_qh);
    cudaGetSymbolAddress((void**)&kh, g_kh);   cudaGetSymbolAddress((void**)&kl, g_kl);
    cudaGetSymbolAddress((void**)&vh, g_vh);   cudaGetSymbolAddress((void**)&vl, g_vl);
    cudaGetSymbolAddress((void**)&ath, g_ath); cudaGetSymbolAddress((void**)&atl, g_atl);
    cudaGetSymbolAddress((void**)&vih, g_vih); cudaGetSymbolAddress((void**)&vil, g_vil);
    cudaGetSymbolAddress((void**)&wh, g_wh);

    cudaFuncSetAttribute(gemm_mma<0>, cudaFuncAttributeMaxDynamicSharedMemorySize, 2 * GSTAGE);
    cudaFuncSetAttribute(gemm_mma<2>, cudaFuncAttributeMaxDynamicSharedMemorySize, 2 * GSTAGE);
    cudaFuncSetAttribute(gemm_mma<3>, cudaFuncAttributeMaxDynamicSharedMemorySize, 2 * GSTAGE);
    cudaFuncSetAttribute(attn_mma, cudaFuncAttributeMaxDynamicSharedMemorySize, SMEM_ATTN);

    pack_mask_kernel<<<(B_*S_*S_) / 256, 256>>>(mask);
    split_act_kernel<<<(M_*E_/4) / 256, 256>>>(query, xh, xl);
    split_act_kernel<<<(M_*E_/4) / 256, 256>>>(value, vih, vil);
    dim3 wgrid(32, 32, 4 * L_), wblk(32, 8);
    split_wT_all_kernel<<<wgrid, wblk>>>(Wq, Wk, Wv, Wo, wh);

    // mega K/V projection: all layers, one launch
    dim3 megagrid(16 * L_, 32);     // 2048 CTAs
    gemm_mma<3><<<megagrid, 512, 2*GSTAGE>>>(vih, vil, wh, bk, bv, nullptr,
                                             kh, kl, vh, vl);

    dim3 qgrid(8, 32);              // 256 CTAs
    dim3 agrid(S_/128, H_, B_);
    const size_t kvstride = (size_t)M_ * E_;
    for (int l = 0; l < L_; l++) {
        size_t w0 = ((size_t)(l*4 + 0)) << 20;
        size_t w3 = ((size_t)(l*4 + 3)) << 20;
        gemm_mma<2><<<qgrid, 512, 2*GSTAGE>>>(xh, xl, wh + w0,
                                              bq + l*E_, nullptr, nullptr,
                                              qh, nullptr, nullptr, nullptr);
        attn_mma<<<agrid, 512, SMEM_ATTN>>>(qh,
                                            kh + l*kvstride, kl + l*kvstride,
                                            vh + l*kvstride, vl + l*kvstride,
                                            ath, atl);
        gemm_mma<0><<<qgrid, 512, 2*GSTAGE>>>(ath, atl, wh + w3,
                                              bo + l*E_, nullptr, proj,
                                              nullptr, nullptr, nullptr, nullptr);
        add_ln_kernel<<<M_, 256>>>(proj, (l == 0) ? query : x,
                                   gamma + l*E_, beta + l*E_,
                                   (l == L_-1) ? out : x, xh, xl);
    }
}

// round 15
// speedup vs baseline: 1.0104x; 1.0104x over previous
#include <cuda_runtime.h>
#include <cuda_fp16.h>
#include <cstdint>

#define B_ 4
#define S_ 2048
#define E_ 1024
#define H_ 16
#define D_ 64
#define L_ 4
#define M_ (B_*S_)          // 8192 rows
#define PW_ (S_/32)         // 64 mask words per row
#define SCALE_ 0.03125f     // E^-0.5
#define EPS_ 1e-5f

// ---------------- scratch (__device__ globals: allocation-free rule) -------
__device__ float g_x[M_*E_];
__device__ float g_proj[M_*E_];
__device__ unsigned g_pmask[B_*S_*PW_];
__device__ __half g_xh[M_*E_],  g_xl[M_*E_];
__device__ __half g_qh[M_*E_];
__device__ __half g_kh[L_*M_*E_], g_kl[L_*M_*E_];   // all layers (value is layer-invariant)
__device__ __half g_vh[L_*M_*E_], g_vl[L_*M_*E_];
__device__ __half g_ath[M_*E_], g_atl[M_*E_];
__device__ __half g_vih[M_*E_], g_vil[M_*E_];
__device__ __half g_wh[L_*4*E_*E_];   // weights [N][K] (transposed), fp16

// ============================ portable PTX helpers ==========================
__device__ __forceinline__ uint32_t smem_to_u32(const void* p) {
    uint32_t a;
    asm("{ .reg .u64 t; cvta.to.shared.u64 t, %1; cvt.u32.u64 %0, t; }"
        : "=r"(a) : "l"(p));
    return a;
}
#define SMEM_SWIZZLE_128B(o) ((o) ^ (((o) >> 3) & 0x70))

__device__ __forceinline__ void cp16(uint32_t dst, const void* src) {
    asm volatile("cp.async.cg.shared.global [%0], [%1], 16;" :: "r"(dst), "l"(src) : "memory");
}
#define CP_COMMIT() asm volatile("cp.async.commit_group;" ::: "memory")
#define CP_WAIT0()  asm volatile("cp.async.wait_group 0;" ::: "memory")
#define CP_WAIT1()  asm volatile("cp.async.wait_group 1;" ::: "memory")

__device__ __forceinline__ void ldsm4(uint32_t* r, uint32_t a) {
    asm volatile("ldmatrix.sync.aligned.m8n8.x4.shared.b16 {%0,%1,%2,%3}, [%4];"
        : "=r"(r[0]), "=r"(r[1]), "=r"(r[2]), "=r"(r[3]) : "r"(a));
}
__device__ __forceinline__ void ldsm4t(uint32_t* r, uint32_t a) {
    asm volatile("ldmatrix.sync.aligned.m8n8.x4.trans.shared.b16 {%0,%1,%2,%3}, [%4];"
        : "=r"(r[0]), "=r"(r[1]), "=r"(r[2]), "=r"(r[3]) : "r"(a));
}
// D += A(16x16) * B(16x8), fp16 in, fp32 accum
__device__ __forceinline__ void mma_f16(float* c, const uint32_t* a, const uint32_t* b) {
    asm volatile("mma.sync.aligned.m16n8k16.row.col.f32.f16.f16.f32 "
        "{%0,%1,%2,%3}, {%4,%5,%6,%7}, {%8,%9}, {%0,%1,%2,%3};"
        : "+f"(c[0]), "+f"(c[1]), "+f"(c[2]), "+f"(c[3])
        : "r"(a[0]), "r"(a[1]), "r"(a[2]), "r"(a[3]), "r"(b[0]), "r"(b[1]));
}
__device__ __forceinline__ void split2h(float v0, float v1, uint32_t& hi, uint32_t& lo) {
    __half2 h = __floats2half2_rn(v0, v1);
    float2 hf = __half22float2(h);
    __half2 l = __floats2half2_rn(v0 - hf.x, v1 - hf.y);
    hi = *(uint32_t*)&h; lo = *(uint32_t*)&l;
}
__device__ __forceinline__ uint32_t pack_h2(float v0, float v1) {
    __half2 h = __floats2half2_rn(v0, v1);
    return *(uint32_t*)&h;
}

// ---------------------------------------------------------------------------
// Fused setup: pack_mask + split_act(query) + split_act(value) + weight
// split/transpose, one launch. Segments decoded from blockIdx.x.
//   [0, 16384)      pack_mask, 1024 elems/CTA
//   [16384, 24576)  split query -> xh/xl
//   [24576, 32768)  split value -> vih/vil
//   [32768, 49152)  W[k][n] -> wh[n][k] fp16, (32x32 tile, layer*4+slot)
// ---------------------------------------------------------------------------
#define SETUP_GRID 49152

__global__ __launch_bounds__(256)
void setup_fused(const int* __restrict__ mask,
                 const float* __restrict__ query, const float* __restrict__ value,
                 const float* __restrict__ Wq, const float* __restrict__ Wk,
                 const float* __restrict__ Wv, const float* __restrict__ Wo,
                 __half* __restrict__ xh, __half* __restrict__ xl,
                 __half* __restrict__ vih, __half* __restrict__ vil,
                 __half* __restrict__ whbase) {
    __shared__ float t[32][33];
    const int bid = blockIdx.x, tid = threadIdx.x;
    if (bid < 16384) {                       // ---- pack mask ----
        #pragma unroll
        for (int j = 0; j < 4; j++) {
            unsigned i = (unsigned)bid * 1024u + j * 256u + tid;
            unsigned word = __ballot_sync(0xffffffffu, mask[i] == 1);
            if ((tid & 31) == 0) g_pmask[i >> 5] = word;
        }
    } else if (bid < 32768) {                // ---- split activations ----
        int vb = bid - 16384;
        const float* src = (vb < 8192) ? query : value;
        __half* hi = (vb < 8192) ? xh : vih;
        __half* lo = (vb < 8192) ? xl : vil;
        size_t i = (size_t)(vb & 8191) * 256 + tid;
        float4 v = ((const float4*)src)[i];
        uint32_t h01, l01, h23, l23;
        split2h(v.x, v.y, h01, l01);
        split2h(v.z, v.w, h23, l23);
        ((uint2*)hi)[i] = make_uint2(h01, h23);
        ((uint2*)lo)[i] = make_uint2(l01, l23);
    } else {                                 // ---- weight split/transpose ----
        int vb = bid - 32768;
        int z = vb >> 10, slot = z & 3, layer = z >> 2;
        const float* Wb = (slot == 0) ? Wq : (slot == 1) ? Wk : (slot == 2) ? Wv : Wo;
        const float* W = Wb + (size_t)layer * E_ * E_;
        __half* hi = whbase + ((size_t)z << 20);
        int bn = (vb & 31) * 32, bk = ((vb >> 5) & 31) * 32;
        int tx = tid & 31, ty = tid >> 5;
        #pragma unroll
        for (int i = 0; i < 32; i += 8)
            t[ty + i][tx] = W[(size_t)(bk + ty + i) * E_ + bn + tx];
        __syncthreads();
        #pragma unroll
        for (int i = 0; i < 32; i += 8)
            hi[(size_t)(bn + ty + i) * E_ + bk + tx] = __float2half(t[tx][ty + i]);
    }
}

// ---------------------------------------------------------------------------
// fp16x2 MMA GEMM: C = (Ah+Al) @ Wh^T + bias. CTA tile 256x128, 512 threads,
// warp tile 64x32, K-chunk 64, double-buffered cp.async.
// MODE 0: fp32 out. MODE 2: fp16 hi only.
// MODE 3: mega K/V — bn decodes (layer, K-or-V, col-block); fp16 hi/lo out.
// ---------------------------------------------------------------------------
#define GS_AL 32768
#define GS_W  65536
#define GSTAGE 81920

__device__ __forceinline__ void gemm_load_stage(uint32_t base,
        const char* gA_h, const char* gA_l, const char* gW,
        int kc, int tid) {
    size_t co = (size_t)kc * 128;
    #pragma unroll
    for (int i = 0; i < 4; i++) {           // A: 256 rows x 8 seg, hi+lo
        int idx = tid + i * 512;
        int r = idx >> 3, sg = idx & 7;
        uint32_t so = SMEM_SWIZZLE_128B((uint32_t)(r * 128 + sg * 16));
        size_t go = (size_t)r * 2048 + co + sg * 16;
        cp16(base + so, gA_h + go);
        cp16(base + GS_AL + so, gA_l + go);
    }
    #pragma unroll
    for (int i = 0; i < 2; i++) {           // W: 128 rows x 8 seg
        int idx = tid + i * 512;
        int r = idx >> 3, sg = idx & 7;
        uint32_t so = SMEM_SWIZZLE_128B((uint32_t)(r * 128 + sg * 16));
        cp16(base + GS_W + so, gW + (size_t)r * 2048 + co + sg * 16);
    }
}

template<int MODE>
__global__ __launch_bounds__(512, 1)
void gemm_mma(const __half* __restrict__ Ah, const __half* __restrict__ Al,
              const __half* __restrict__ Wh,
              const float* __restrict__ bias, const float* __restrict__ bias2,
              float* __restrict__ C,
              __half* __restrict__ Hh, __half* __restrict__ Hl,
              __half* __restrict__ Hh2, __half* __restrict__ Hl2) {
    extern __shared__ char smem[];
    const uint32_t sb = smem_to_u32(smem);
    const int tid = threadIdx.x, lane = tid & 31, w = tid >> 5;
    const int bm = blockIdx.y, bn = blockIdx.x;
    const int m0 = (w & 3) * 64, n0 = (w >> 2) * 32;

    const char* gA_h = (const char*)(Ah + (size_t)bm * 256 * E_);
    const char* gA_l = (const char*)(Al + (size_t)bm * 256 * E_);
    const char* gW;
    const float* bias_sel = bias;
    __half *HhU = Hh, *HlU = Hl;
    int colbase;
    if (MODE == 3) {
        int layer = bn >> 4, sub = bn & 15;
        int slot = sub >> 3, wcol = sub & 7;
        gW = (const char*)(Wh + (((size_t)(layer * 4 + 1 + slot)) << 20)
                              + (size_t)wcol * 128 * E_);
        bias_sel = (slot ? bias2 : bias) + layer * E_;
        HhU = (slot ? Hh2 : Hh) + (size_t)layer * ((size_t)M_ * E_);
        HlU = (slot ? Hl2 : Hl) + (size_t)layer * ((size_t)M_ * E_);
        colbase = wcol * 128;
    } else {
        gW = (const char*)(Wh + (size_t)bn * 128 * E_);
        colbase = bn * 128;
    }

    const int arow = m0 + (lane & 15);
    const uint32_t a_kb = (uint32_t)((lane >> 4) * 16);
    const uint32_t axor = (uint32_t)((arow & 7) << 4);
    const int brow = n0 + (lane & 7) + ((lane >> 4) << 3);
    const uint32_t b_kb = (uint32_t)(((lane >> 3) & 1) * 16);
    const uint32_t bxor = (uint32_t)((brow & 7) << 4);

    float c[4][4][4];
    #pragma unroll
    for (int i = 0; i < 4; i++)
        #pragma unroll
        for (int j = 0; j < 4; j++)
            #pragma unroll
            for (int q = 0; q < 4; q++) c[i][j][q] = 0.f;

    gemm_load_stage(sb, gA_h, gA_l, gW, 0, tid);
    CP_COMMIT();

    for (int kc = 0; kc < 16; kc++) {
        uint32_t stg = sb + (uint32_t)((kc & 1) * GSTAGE);
        CP_WAIT0();
        __syncthreads();            // stage kc visible; all warps done with kc-1
        if (kc + 1 < 16) {
            gemm_load_stage(sb + (uint32_t)(((kc + 1) & 1) * GSTAGE),
                            gA_h, gA_l, gW, kc + 1, tid);
            CP_COMMIT();
        }
        #pragma unroll
        for (int kk = 0; kk < 4; kk++) {
            uint32_t ah[4][4], al[4][4], bh[2][4];
            #pragma unroll
            for (int mt = 0; mt < 4; mt++) {
                uint32_t ra = stg + (uint32_t)((arow + mt * 16) * 128)
                                  + (((uint32_t)(kk * 32) + a_kb) ^ axor);
                ldsm4(ah[mt], ra);
                ldsm4(al[mt], ra + GS_AL);
            }
            #pragma unroll
            for (int p = 0; p < 2; p++) {
                uint32_t rb = stg + GS_W + (uint32_t)((brow + p * 16) * 128)
                                  + (((uint32_t)(kk * 32) + b_kb) ^ bxor);
                ldsm4(bh[p], rb);
            }
            #pragma unroll
            for (int mt = 0; mt < 4; mt++)
                #pragma unroll
                for (int p = 0; p < 2; p++)
                    #pragma unroll
                    for (int t = 0; t < 2; t++)
                        mma_f16(c[mt][p*2+t], ah[mt], &bh[p][t*2]);
            #pragma unroll
            for (int mt = 0; mt < 4; mt++)
                #pragma unroll
                for (int p = 0; p < 2; p++)
                    #pragma unroll
                    for (int t = 0; t < 2; t++)
                        mma_f16(c[mt][p*2+t], al[mt], &bh[p][t*2]);
        }
    }

    // epilogue
    const int g = lane >> 2, tg = lane & 3;
    #pragma unroll
    for (int nt = 0; nt < 4; nt++) {
        int col = colbase + n0 + nt * 8 + 2 * tg;
        float b0 = bias_sel[col], b1 = bias_sel[col + 1];
        #pragma unroll
        for (int mt = 0; mt < 4; mt++) {
            int row = bm * 256 + m0 + mt * 16 + g;
            float v0 = c[mt][nt][0] + b0, v1 = c[mt][nt][1] + b1;
            float v2 = c[mt][nt][2] + b0, v3 = c[mt][nt][3] + b1;
            size_t i0 = (size_t)row * E_ + col;
            size_t i1 = i0 + (size_t)8 * E_;
            if (MODE == 3) {
                uint32_t h01, l01, h23, l23;
                split2h(v0, v1, h01, l01);
                split2h(v2, v3, h23, l23);
                *(uint32_t*)(HhU + i0) = h01; *(uint32_t*)(HlU + i0) = l01;
                *(uint32_t*)(HhU + i1) = h23; *(uint32_t*)(HlU + i1) = l23;
            } else if (MODE == 2) {
                *(uint32_t*)(HhU + i0) = pack_h2(v0, v1);
                *(uint32_t*)(HhU + i1) = pack_h2(v2, v3);
            } else {
                *(float2*)(C + i0) = make_float2(v0, v1);
                *(float2*)(C + i1) = make_float2(v2, v3);
            }
        }
    }
}

// ---------------------------------------------------------------------------
// Fused ReLU attention, fp16 2-term (Qh@(Kh+Kl), Sh@(Vh+Vl)), all f32 accum.
// 512 threads; warp (qg 0-7, kvh 0-1): 16q x 64kv per chunk; Q resident.
// smem: Qh 16K | 3 x (Kh|Kl|Vh|Vl 16K each) = 208K
// ---------------------------------------------------------------------------
#define AKV(s) (16384 + (s) * 65536)
#define AKL 16384
#define AVH 32768
#define SMEM_ATTN 212992

__device__ __forceinline__ void attn_load_kv(uint32_t base,
        const char* gK_h, const char* gK_l, const char* gV_h, const char* gV_l,
        int kc, int tid) {
    #pragma unroll
    for (int i = 0; i < 2; i++) {
        int idx = tid + i * 512;
        int r = idx >> 3, sg = idx & 7;
        uint32_t so = SMEM_SWIZZLE_128B((uint32_t)(r * 128 + sg * 16));
        size_t go = (size_t)(kc * 128 + r) * 2048 + sg * 16;
        cp16(base + so,         gK_h + go);
        cp16(base + AKL + so,   gK_l + go);
        cp16(base + AVH + so,   gV_h + go);
        cp16(base + 49152 + so, gV_l + go);
    }
}

__global__ __launch_bounds__(512, 1)
void attn_mma(const __half* __restrict__ qh,
              const __half* __restrict__ kh, const __half* __restrict__ kl,
              const __half* __restrict__ vh, const __half* __restrict__ vl,
              __half* __restrict__ oh, __half* __restrict__ ol) {
    extern __shared__ char smem[];
    const uint32_t sb = smem_to_u32(smem);
    const int tid = threadIdx.x, lane = tid & 31, w = tid >> 5;
    const int qg = w & 7, kvh = w >> 3;
    const int qt = blockIdx.x, h = blockIdx.y, b = blockIdx.z;
    const int q0 = qt * 128;
    const int g = lane >> 2, tg = lane & 3;

    const size_t hb = ((size_t)b * S_) * E_ + h * D_;
    const char* gQ_h = (const char*)(qh + hb);
    const char* gK_h = (const char*)(kh + hb);
    const char* gK_l = (const char*)(kl + hb);
    const char* gV_h = (const char*)(vh + hb);
    const char* gV_l = (const char*)(vl + hb);
    const unsigned* pm = g_pmask + (size_t)b * S_ * PW_;

    // prologue: group0 = Q + KV0, group1 = KV1
    #pragma unroll
    for (int i = 0; i < 2; i++) {
        int idx = tid + i * 512;
        int r = idx >> 3, sg = idx & 7;
        uint32_t so = SMEM_SWIZZLE_128B((uint32_t)(r * 128 + sg * 16));
        cp16(sb + so, gQ_h + (size_t)(q0 + r) * 2048 + sg * 16);
    }
    attn_load_kv(sb + AKV(0), gK_h, gK_l, gV_h, gV_l, 0, tid);
    CP_COMMIT();
    attn_load_kv(sb + AKV(1), gK_h, gK_l, gV_h, gV_l, 1, tid);
    CP_COMMIT();

    // fragment addressing
    const int arow = qg * 16 + (lane & 15);
    const uint32_t a_kb = (uint32_t)((lane >> 4) * 16);
    const uint32_t lxor = (uint32_t)((lane & 7) << 4);
    const int brow = kvh * 64 + (lane & 7) + ((lane >> 4) << 3);   // + p*16
    const uint32_t b_kb = (uint32_t)(((lane >> 3) & 1) * 16);
    const int vrow = kvh * 64 + (lane & 15);            // + j*16
    const uint32_t vdb = (uint32_t)((lane >> 4) * 16);
    const int r0 = q0 + qg * 16 + g;                    // thread's q rows: r0, r0+8

    uint32_t qfh[4][4];                                 // Q fragments, resident
    float c2[8][4];                                     // O partial (16q x 64d)
    #pragma unroll
    for (int j = 0; j < 8; j++)
        #pragma unroll
        for (int q = 0; q < 4; q++) c2[j][q] = 0.f;

    for (int kc = 0; kc < 16; kc++) {
        uint32_t kv = sb + AKV(kc % 3);
        if (kc < 15) CP_WAIT1(); else CP_WAIT0();
        __syncthreads();            // stage kc visible; all warps done with kc-1
        if (kc + 2 < 16) {
            attn_load_kv(sb + AKV((kc + 2) % 3), gK_h, gK_l, gV_h, gV_l, kc + 2, tid);
            CP_COMMIT();
        }
        if (kc == 0) {              // Q fragments (arrived with group0)
            #pragma unroll
            for (int kk = 0; kk < 4; kk++) {
                uint32_t ra = sb + (uint32_t)(arow * 128)
                                 + (((uint32_t)(kk * 32) + a_kb) ^ lxor);
                ldsm4(qfh[kk], ra);
            }
        }

        // ---- stage 1: S(16q x 64kv) = Qh @ (Kh + Kl)^T ----
        float c1[8][4];
        #pragma unroll
        for (int j = 0; j < 8; j++)
            #pragma unroll
            for (int q = 0; q < 4; q++) c1[j][q] = 0.f;
        #pragma unroll
        for (int kk = 0; kk < 4; kk++) {
            #pragma unroll
            for (int p = 0; p < 4; p++) {
                uint32_t khf[4], klf[4];
                uint32_t rb = kv + (uint32_t)((brow + p * 16) * 128)
                                 + (((uint32_t)(kk * 32) + b_kb) ^ lxor);
                ldsm4(khf, rb);
                ldsm4(klf, rb + AKL);
                #pragma unroll
                for (int t = 0; t < 2; t++)
                    mma_f16(c1[p*2+t], qfh[kk], &khf[t*2]);
                #pragma unroll
                for (int t = 0; t < 2; t++)
                    mma_f16(c1[p*2+t], qfh[kk], &klf[t*2]);
            }
        }

        // ---- mask + relu + scale (registers) ----
        {
            size_t mb = (size_t)r0 * PW_ + kc * 4 + kvh * 2;
            unsigned m0a = pm[mb],         m0b = pm[mb + 1];
            unsigned m1a = pm[mb + PW_*8], m1b = pm[mb + PW_*8 + 1];
            #pragma unroll
            for (int nt = 0; nt < 8; nt++) {
                int col = nt * 8 + 2 * tg;
                int bit = col & 31;
                unsigned w0 = (col < 32) ? m0a : m0b;
                unsigned w1 = (col < 32) ? m1a : m1b;
                c1[nt][0] = ((w0 >> bit) & 1u)       ? 0.f : fmaxf(c1[nt][0] * SCALE_, 0.f);
                c1[nt][1] = ((w0 >> (bit + 1)) & 1u) ? 0.f : fmaxf(c1[nt][1] * SCALE_, 0.f);
                c1[nt][2] = ((w1 >> bit) & 1u)       ? 0.f : fmaxf(c1[nt][2] * SCALE_, 0.f);
                c1[nt][3] = ((w1 >> (bit + 1)) & 1u) ? 0.f : fmaxf(c1[nt][3] * SCALE_, 0.f);
            }
        }

        // ---- stage 2: O += Sh @ (Vh + Vl) ----
        #pragma unroll
        for (int j = 0; j < 4; j++) {
            uint32_t sh[4];
            sh[0] = pack_h2(c1[2*j][0],   c1[2*j][1]);
            sh[1] = pack_h2(c1[2*j][2],   c1[2*j][3]);
            sh[2] = pack_h2(c1[2*j+1][0], c1[2*j+1][1]);
            sh[3] = pack_h2(c1[2*j+1][2], c1[2*j+1][3]);
            #pragma unroll
            for (int p = 0; p < 4; p++) {
                uint32_t vhf[4], vlf[4];
                uint32_t off = (uint32_t)((vrow + j * 16) * 128) + (uint32_t)(p * 32) + vdb;
                uint32_t rb = kv + AVH + SMEM_SWIZZLE_128B(off);
                ldsm4t(vhf, rb);
                ldsm4t(vlf, rb + AKL);
                #pragma unroll
                for (int t = 0; t < 2; t++)
                    mma_f16(c2[p*2+t], sh, &vhf[t*2]);
                #pragma unroll
                for (int t = 0; t < 2; t++)
                    mma_f16(c2[p*2+t], sh, &vlf[t*2]);
            }
        }
    }

    // ---- cross-warp O reduction over kvh, then epilogue ----
    __syncthreads();                       // all reads of KV buffers done
    float* redp = (float*)(smem + 16384 + qg * 4096);   // 16x64 fp32 per q-group
    if (kvh == 1) {
        #pragma unroll
        for (int nt = 0; nt < 8; nt++) {
            int cidx = nt * 8 + 2 * tg;
            *(float2*)(redp + g * 64 + cidx) = make_float2(c2[nt][0], c2[nt][1]);
            *(float2*)(redp + (g + 8) * 64 + cidx) = make_float2(c2[nt][2], c2[nt][3]);
        }
    }
    __syncthreads();
    if (kvh == 0) {
        #pragma unroll
        for (int nt = 0; nt < 8; nt++) {
            int cidx = nt * 8 + 2 * tg;
            float2 p0 = *(float2*)(redp + g * 64 + cidx);
            float2 p1 = *(float2*)(redp + (g + 8) * 64 + cidx);
            float v0 = c2[nt][0] + p0.x, v1 = c2[nt][1] + p0.y;
            float v2 = c2[nt][2] + p1.x, v3 = c2[nt][3] + p1.y;
            size_t i0 = ((size_t)b * S_ + r0) * E_ + h * D_ + cidx;
            size_t i1 = i0 + (size_t)8 * E_;
            uint32_t h01, l01, h23, l23;
            split2h(v0, v1, h01, l01);
            split2h(v2, v3, h23, l23);
            *(uint32_t*)(oh + i0) = h01; *(uint32_t*)(ol + i0) = l01;
            *(uint32_t*)(oh + i1) = h23; *(uint32_t*)(ol + i1) = l23;
        }
    }
}

// ---------------------------------------------------------------------------
// out = LayerNorm(a + res)*gamma + beta ; also writes fp16 hi/lo of out.
// Two rows per CTA: 256 threads, 128/row, 8 floats/thread.
// ---------------------------------------------------------------------------
__global__ __launch_bounds__(256)
void add_ln_kernel(const float* __restrict__ a, const float* __restrict__ res,
                   const float* __restrict__ gamma, const float* __restrict__ beta,
                   float* __restrict__ out,
                   __half* __restrict__ oh, __half* __restrict__ ol) {
    __shared__ float red[8];
    __shared__ float bcast[2];
    const int tid = threadIdx.x;
    const int half = tid >> 7, t = tid & 127;
    const int row = blockIdx.x * 2 + half;
    const int lane = tid & 31, wid = tid >> 5;     // wids 0-3 row0, 4-7 row1
    const float* ap = a + (size_t)row * E_ + t * 8;
    const float* xp = res + (size_t)row * E_ + t * 8;
    float4 va0 = *(const float4*)ap,       vx0 = *(const float4*)xp;
    float4 va1 = *(const float4*)(ap + 4), vx1 = *(const float4*)(xp + 4);
    float v[8];
    v[0] = va0.x + vx0.x; v[1] = va0.y + vx0.y; v[2] = va0.z + vx0.z; v[3] = va0.w + vx0.w;
    v[4] = va1.x + vx1.x; v[5] = va1.y + vx1.y; v[6] = va1.z + vx1.z; v[7] = va1.w + vx1.w;
    float s = 0.f;
    #pragma unroll
    for (int i = 0; i < 8; i++) s += v[i];
    #pragma unroll
    for (int off = 16; off > 0; off >>= 1) s += __shfl_xor_sync(~0u, s, off);
    if (lane == 0) red[wid] = s;
    __syncthreads();
    if (t == 0) {
        float tt = 0.f;
        #pragma unroll
        for (int i = 0; i < 4; i++) tt += red[half * 4 + i];
        bcast[half] = tt;
    }
    __syncthreads();
    float mean = bcast[half] * (1.0f / E_);
    float d[8], vs = 0.f;
    #pragma unroll
    for (int i = 0; i < 8; i++) { d[i] = v[i] - mean; vs += d[i] * d[i]; }
    #pragma unroll
    for (int off = 16; off > 0; off >>= 1) vs += __shfl_xor_sync(~0u, vs, off);
    __syncthreads();
    if (lane == 0) red[wid] = vs;
    __syncthreads();
    if (t == 0) {
        float tt = 0.f;
        #pragma unroll
        for (int i = 0; i < 4; i++) tt += red[half * 4 + i];
        bcast[half] = tt;
    }
    __syncthreads();
    float inv = rsqrtf(bcast[half] * (1.0f / E_) + EPS_);
    float o[8];
    #pragma unroll
    for (int i = 0; i < 8; i += 4) {
        float4 gq = *(const float4*)(gamma + t * 8 + i);
        float4 bt = *(const float4*)(beta + t * 8 + i);
        o[i]   = d[i]   * inv * gq.x + bt.x;
        o[i+1] = d[i+1] * inv * gq.y + bt.y;
        o[i+2] = d[i+2] * inv * gq.z + bt.z;
        o[i+3] = d[i+3] * inv * gq.w + bt.w;
    }
    size_t i0 = (size_t)row * E_ + t * 8;
    *(float4*)(out + i0)     = make_float4(o[0], o[1], o[2], o[3]);
    *(float4*)(out + i0 + 4) = make_float4(o[4], o[5], o[6], o[7]);
    uint32_t h01, l01, h23, l23, h45, l45, h67, l67;
    split2h(o[0], o[1], h01, l01);
    split2h(o[2], o[3], h23, l23);
    split2h(o[4], o[5], h45, l45);
    split2h(o[6], o[7], h67, l67);
    *(uint4*)(oh + i0) = make_uint4(h01, h23, h45, h67);
    *(uint4*)(ol + i0) = make_uint4(l01, l23, l45, l67);
}

// ---------------------------------------------------------------------------
extern "C" void kernel_launch(void* const* d_in, const int* in_sizes, int n_in,
                              void* d_out, int out_size) {
    const float* query = (const float*)d_in[0];
    const float* value = (const float*)d_in[1];
    const int*   mask  = (const int*)d_in[2];
    const float* Wq = (const float*)d_in[3];
    const float* Wk = (const float*)d_in[4];
    const float* Wv = (const float*)d_in[5];
    const float* Wo = (const float*)d_in[6];
    const float* bq = (const float*)d_in[7];
    const float* bk = (const float*)d_in[8];
    const float* bv = (const float*)d_in[9];
    const float* bo = (const float*)d_in[10];
    const float* gamma = (const float*)d_in[11];
    const float* beta  = (const float*)d_in[12];
    float* out = (float*)d_out;

    float *x, *proj;
    cudaGetSymbolAddress((void**)&x,    g_x);
    cudaGetSymbolAddress((void**)&proj, g_proj);
    __half *xh, *xl, *ath, *atl, *vih, *vil, *wh;
    __half *qh, *kh, *kl, *vh, *vl;
    cudaGetSymbolAddress((void**)&xh, g_xh);   cudaGetSymbolAddress((void**)&xl, g_xl);
    cudaGetSymbolAddress((void**)&qh, g_qh);
    cudaGetSymbolAddress((void**)&kh, g_kh);   cudaGetSymbolAddress((void**)&kl, g_kl);
    cudaGetSymbolAddress((void**)&vh, g_vh);   cudaGetSymbolAddress((void**)&vl, g_vl);
    cudaGetSymbolAddress((void**)&ath, g_ath); cudaGetSymbolAddress((void**)&atl, g_atl);
    cudaGetSymbolAddress((void**)&vih, g_vih); cudaGetSymbolAddress((void**)&vil, g_vil);
    cudaGetSymbolAddress((void**)&wh, g_wh);

    cudaFuncSetAttribute(gemm_mma<0>, cudaFuncAttributeMaxDynamicSharedMemorySize, 2 * GSTAGE);
    cudaFuncSetAttribute(gemm_mma<2>, cudaFuncAttributeMaxDynamicSharedMemorySize, 2 * GSTAGE);
    cudaFuncSetAttribute(gemm_mma<3>, cudaFuncAttributeMaxDynamicSharedMemorySize, 2 * GSTAGE);
    cudaFuncSetAttribute(attn_mma, cudaFuncAttributeMaxDynamicSharedMemorySize, SMEM_ATTN);

    // fused setup: mask pack + activation splits + weight split/transpose
    setup_fused<<<SETUP_GRID, 256>>>(mask, query, value, Wq, Wk, Wv, Wo,
                                     xh, xl, vih, vil, wh);

    // mega K/V projection: all layers, one launch
    dim3 megagrid(16 * L_, 32);     // 2048 CTAs
    gemm_mma<3><<<megagrid, 512, 2*GSTAGE>>>(vih, vil, wh, bk, bv, nullptr,
                                             kh, kl, vh, vl);

    dim3 qgrid(8, 32);              // 256 CTAs
    dim3 agrid(S_/128, H_, B_);
    const size_t kvstride = (size_t)M_ * E_;
    for (int l = 0; l < L_; l++) {
        size_t w0 = ((size_t)(l*4 + 0)) << 20;
        size_t w3 = ((size_t)(l*4 + 3)) << 20;
        gemm_mma<2><<<qgrid, 512, 2*GSTAGE>>>(xh, xl, wh + w0,
                                              bq + l*E_, nullptr, nullptr,
                                              qh, nullptr, nullptr, nullptr);
        attn_mma<<<agrid, 512, SMEM_ATTN>>>(qh,
                                            kh + l*kvstride, kl + l*kvstride,
                                            vh + l*kvstride, vl + l*kvstride,
                                            ath, atl);
        gemm_mma<0><<<qgrid, 512, 2*GSTAGE>>>(ath, atl, wh + w3,
                                              bo + l*E_, nullptr, proj,
                                              nullptr, nullptr, nullptr, nullptr);
        add_ln_kernel<<<M_/2, 256>>>(proj, (l == 0) ? query : x,
                                     gamma + l*E_, beta + l*E_,
                                     (l == L_-1) ? out : x, xh, xl);
    }
}

// round 16
// speedup vs baseline: 1.0460x; 1.0352x over previous
#include <cuda_runtime.h>
#include <cuda_fp16.h>
#include <cstdint>

#define B_ 4
#define S_ 2048
#define E_ 1024
#define H_ 16
#define D_ 64
#define L_ 4
#define M_ (B_*S_)          // 8192 rows
#define PW_ (S_/32)         // 64 mask words per row
#define SCALE_ 0.03125f     // E^-0.5 = 2^-5 (exact in fp16; folded into Q proj)
#define EPS_ 1e-5f

// ---------------- scratch (__device__ globals: allocation-free rule) -------
__device__ float g_x[M_*E_];
__device__ float g_proj[M_*E_];
__device__ unsigned g_pmask[B_*S_*PW_];
__device__ __half g_xh[M_*E_],  g_xl[M_*E_];
__device__ __half g_qh[M_*E_];
__device__ __half g_kh[L_*M_*E_], g_kl[L_*M_*E_];   // all layers (value is layer-invariant)
__device__ __half g_vh[L_*M_*E_], g_vl[L_*M_*E_];
__device__ __half g_ath[M_*E_], g_atl[M_*E_];
__device__ __half g_vih[M_*E_], g_vil[M_*E_];
__device__ __half g_wh[L_*4*E_*E_];   // weights [N][K] (transposed), fp16

// ============================ portable PTX helpers ==========================
__device__ __forceinline__ uint32_t smem_to_u32(const void* p) {
    uint32_t a;
    asm("{ .reg .u64 t; cvta.to.shared.u64 t, %1; cvt.u32.u64 %0, t; }"
        : "=r"(a) : "l"(p));
    return a;
}
#define SMEM_SWIZZLE_128B(o) ((o) ^ (((o) >> 3) & 0x70))

__device__ __forceinline__ void cp16(uint32_t dst, const void* src) {
    asm volatile("cp.async.cg.shared.global [%0], [%1], 16;" :: "r"(dst), "l"(src) : "memory");
}
#define CP_COMMIT() asm volatile("cp.async.commit_group;" ::: "memory")
#define CP_WAIT0()  asm volatile("cp.async.wait_group 0;" ::: "memory")
#define CP_WAIT1()  asm volatile("cp.async.wait_group 1;" ::: "memory")

__device__ __forceinline__ void ldsm4(uint32_t* r, uint32_t a) {
    asm volatile("ldmatrix.sync.aligned.m8n8.x4.shared.b16 {%0,%1,%2,%3}, [%4];"
        : "=r"(r[0]), "=r"(r[1]), "=r"(r[2]), "=r"(r[3]) : "r"(a));
}
__device__ __forceinline__ void ldsm4t(uint32_t* r, uint32_t a) {
    asm volatile("ldmatrix.sync.aligned.m8n8.x4.trans.shared.b16 {%0,%1,%2,%3}, [%4];"
        : "=r"(r[0]), "=r"(r[1]), "=r"(r[2]), "=r"(r[3]) : "r"(a));
}
// D += A(16x16) * B(16x8), fp16 in, fp32 accum
__device__ __forceinline__ void mma_f16(float* c, const uint32_t* a, const uint32_t* b) {
    asm volatile("mma.sync.aligned.m16n8k16.row.col.f32.f16.f16.f32 "
        "{%0,%1,%2,%3}, {%4,%5,%6,%7}, {%8,%9}, {%0,%1,%2,%3};"
        : "+f"(c[0]), "+f"(c[1]), "+f"(c[2]), "+f"(c[3])
        : "r"(a[0]), "r"(a[1]), "r"(a[2]), "r"(a[3]), "r"(b[0]), "r"(b[1]));
}
__device__ __forceinline__ void split2h(float v0, float v1, uint32_t& hi, uint32_t& lo) {
    __half2 h = __floats2half2_rn(v0, v1);
    float2 hf = __half22float2(h);
    __half2 l = __floats2half2_rn(v0 - hf.x, v1 - hf.y);
    hi = *(uint32_t*)&h; lo = *(uint32_t*)&l;
}
__device__ __forceinline__ uint32_t pack_h2(float v0, float v1) {
    __half2 h = __floats2half2_rn(v0, v1);
    return *(uint32_t*)&h;
}

// ---------------------------------------------------------------------------
// Fused setup: pack_mask + split_act(query) + split_act(value) + weight
// split/transpose, one launch. Segments decoded from blockIdx.x.
// ---------------------------------------------------------------------------
#define SETUP_GRID 49152

__global__ __launch_bounds__(256)
void setup_fused(const int* __restrict__ mask,
                 const float* __restrict__ query, const float* __restrict__ value,
                 const float* __restrict__ Wq, const float* __restrict__ Wk,
                 const float* __restrict__ Wv, const float* __restrict__ Wo,
                 __half* __restrict__ xh, __half* __restrict__ xl,
                 __half* __restrict__ vih, __half* __restrict__ vil,
                 __half* __restrict__ whbase) {
    __shared__ float t[32][33];
    const int bid = blockIdx.x, tid = threadIdx.x;
    if (bid < 16384) {                       // ---- pack mask ----
        #pragma unroll
        for (int j = 0; j < 4; j++) {
            unsigned i = (unsigned)bid * 1024u + j * 256u + tid;
            unsigned word = __ballot_sync(0xffffffffu, mask[i] == 1);
            if ((tid & 31) == 0) g_pmask[i >> 5] = word;
        }
    } else if (bid < 32768) {                // ---- split activations ----
        int vb = bid - 16384;
        const float* src = (vb < 8192) ? query : value;
        __half* hi = (vb < 8192) ? xh : vih;
        __half* lo = (vb < 8192) ? xl : vil;
        size_t i = (size_t)(vb & 8191) * 256 + tid;
        float4 v = ((const float4*)src)[i];
        uint32_t h01, l01, h23, l23;
        split2h(v.x, v.y, h01, l01);
        split2h(v.z, v.w, h23, l23);
        ((uint2*)hi)[i] = make_uint2(h01, h23);
        ((uint2*)lo)[i] = make_uint2(l01, l23);
    } else {                                 // ---- weight split/transpose ----
        int vb = bid - 32768;
        int z = vb >> 10, slot = z & 3, layer = z >> 2;
        const float* Wb = (slot == 0) ? Wq : (slot == 1) ? Wk : (slot == 2) ? Wv : Wo;
        const float* W = Wb + (size_t)layer * E_ * E_;
        __half* hi = whbase + ((size_t)z << 20);
        int bn = (vb & 31) * 32, bk = ((vb >> 5) & 31) * 32;
        int tx = tid & 31, ty = tid >> 5;
        #pragma unroll
        for (int i = 0; i < 32; i += 8)
            t[ty + i][tx] = W[(size_t)(bk + ty + i) * E_ + bn + tx];
        __syncthreads();
        #pragma unroll
        for (int i = 0; i < 32; i += 8)
            hi[(size_t)(bn + ty + i) * E_ + bk + tx] = __float2half(t[tx][ty + i]);
    }
}

// ---------------------------------------------------------------------------
// fp16x2 MMA GEMM: C = (Ah+Al) @ Wh^T + bias. CTA tile 256x128, 512 threads,
// warp tile 64x32, K-chunk 64, double-buffered cp.async.
// MODE 0: fp32 out. MODE 2: fp16 hi only, PRESCALED by SCALE_ (Q projection).
// MODE 3: mega K/V — bn decodes (layer, K-or-V, col-block); fp16 hi/lo out.
// ---------------------------------------------------------------------------
#define GS_AL 32768
#define GS_W  65536
#define GSTAGE 81920

__device__ __forceinline__ void gemm_load_stage(uint32_t base,
        const char* gA_h, const char* gA_l, const char* gW,
        int kc, int tid) {
    size_t co = (size_t)kc * 128;
    #pragma unroll
    for (int i = 0; i < 4; i++) {           // A: 256 rows x 8 seg, hi+lo
        int idx = tid + i * 512;
        int r = idx >> 3, sg = idx & 7;
        uint32_t so = SMEM_SWIZZLE_128B((uint32_t)(r * 128 + sg * 16));
        size_t go = (size_t)r * 2048 + co + sg * 16;
        cp16(base + so, gA_h + go);
        cp16(base + GS_AL + so, gA_l + go);
    }
    #pragma unroll
    for (int i = 0; i < 2; i++) {           // W: 128 rows x 8 seg
        int idx = tid + i * 512;
        int r = idx >> 3, sg = idx & 7;
        uint32_t so = SMEM_SWIZZLE_128B((uint32_t)(r * 128 + sg * 16));
        cp16(base + GS_W + so, gW + (size_t)r * 2048 + co + sg * 16);
    }
}

template<int MODE>
__global__ __launch_bounds__(512, 1)
void gemm_mma(const __half* __restrict__ Ah, const __half* __restrict__ Al,
              const __half* __restrict__ Wh,
              const float* __restrict__ bias, const float* __restrict__ bias2,
              float* __restrict__ C,
              __half* __restrict__ Hh, __half* __restrict__ Hl,
              __half* __restrict__ Hh2, __half* __restrict__ Hl2) {
    extern __shared__ char smem[];
    const uint32_t sb = smem_to_u32(smem);
    const int tid = threadIdx.x, lane = tid & 31, w = tid >> 5;
    const int bm = blockIdx.y, bn = blockIdx.x;
    const int m0 = (w & 3) * 64, n0 = (w >> 2) * 32;

    const char* gA_h = (const char*)(Ah + (size_t)bm * 256 * E_);
    const char* gA_l = (const char*)(Al + (size_t)bm * 256 * E_);
    const char* gW;
    const float* bias_sel = bias;
    __half *HhU = Hh, *HlU = Hl;
    int colbase;
    if (MODE == 3) {
        int layer = bn >> 4, sub = bn & 15;
        int slot = sub >> 3, wcol = sub & 7;
        gW = (const char*)(Wh + (((size_t)(layer * 4 + 1 + slot)) << 20)
                              + (size_t)wcol * 128 * E_);
        bias_sel = (slot ? bias2 : bias) + layer * E_;
        HhU = (slot ? Hh2 : Hh) + (size_t)layer * ((size_t)M_ * E_);
        HlU = (slot ? Hl2 : Hl) + (size_t)layer * ((size_t)M_ * E_);
        colbase = wcol * 128;
    } else {
        gW = (const char*)(Wh + (size_t)bn * 128 * E_);
        colbase = bn * 128;
    }

    const int arow = m0 + (lane & 15);
    const uint32_t a_kb = (uint32_t)((lane >> 4) * 16);
    const uint32_t axor = (uint32_t)((arow & 7) << 4);
    const int brow = n0 + (lane & 7) + ((lane >> 4) << 3);
    const uint32_t b_kb = (uint32_t)(((lane >> 3) & 1) * 16);
    const uint32_t bxor = (uint32_t)((brow & 7) << 4);

    float c[4][4][4];
    #pragma unroll
    for (int i = 0; i < 4; i++)
        #pragma unroll
        for (int j = 0; j < 4; j++)
            #pragma unroll
            for (int q = 0; q < 4; q++) c[i][j][q] = 0.f;

    gemm_load_stage(sb, gA_h, gA_l, gW, 0, tid);
    CP_COMMIT();

    for (int kc = 0; kc < 16; kc++) {
        uint32_t stg = sb + (uint32_t)((kc & 1) * GSTAGE);
        CP_WAIT0();
        __syncthreads();            // stage kc visible; all warps done with kc-1
        if (kc + 1 < 16) {
            gemm_load_stage(sb + (uint32_t)(((kc + 1) & 1) * GSTAGE),
                            gA_h, gA_l, gW, kc + 1, tid);
            CP_COMMIT();
        }
        #pragma unroll
        for (int kk = 0; kk < 4; kk++) {
            uint32_t ah[4][4], al[4][4], bh[2][4];
            #pragma unroll
            for (int mt = 0; mt < 4; mt++) {
                uint32_t ra = stg + (uint32_t)((arow + mt * 16) * 128)
                                  + (((uint32_t)(kk * 32) + a_kb) ^ axor);
                ldsm4(ah[mt], ra);
                ldsm4(al[mt], ra + GS_AL);
            }
            #pragma unroll
            for (int p = 0; p < 2; p++) {
                uint32_t rb = stg + GS_W + (uint32_t)((brow + p * 16) * 128)
                                  + (((uint32_t)(kk * 32) + b_kb) ^ bxor);
                ldsm4(bh[p], rb);
            }
            #pragma unroll
            for (int mt = 0; mt < 4; mt++)
                #pragma unroll
                for (int p = 0; p < 2; p++)
                    #pragma unroll
                    for (int t = 0; t < 2; t++)
                        mma_f16(c[mt][p*2+t], ah[mt], &bh[p][t*2]);
            #pragma unroll
            for (int mt = 0; mt < 4; mt++)
                #pragma unroll
                for (int p = 0; p < 2; p++)
                    #pragma unroll
                    for (int t = 0; t < 2; t++)
                        mma_f16(c[mt][p*2+t], al[mt], &bh[p][t*2]);
        }
    }

    // epilogue
    const int g = lane >> 2, tg = lane & 3;
    #pragma unroll
    for (int nt = 0; nt < 4; nt++) {
        int col = colbase + n0 + nt * 8 + 2 * tg;
        float b0 = bias_sel[col], b1 = bias_sel[col + 1];
        #pragma unroll
        for (int mt = 0; mt < 4; mt++) {
            int row = bm * 256 + m0 + mt * 16 + g;
            float v0 = c[mt][nt][0] + b0, v1 = c[mt][nt][1] + b1;
            float v2 = c[mt][nt][2] + b0, v3 = c[mt][nt][3] + b1;
            size_t i0 = (size_t)row * E_ + col;
            size_t i1 = i0 + (size_t)8 * E_;
            if (MODE == 3) {
                uint32_t h01, l01, h23, l23;
                split2h(v0, v1, h01, l01);
                split2h(v2, v3, h23, l23);
                *(uint32_t*)(HhU + i0) = h01; *(uint32_t*)(HlU + i0) = l01;
                *(uint32_t*)(HhU + i1) = h23; *(uint32_t*)(HlU + i1) = l23;
            } else if (MODE == 2) {    // Q projection: fold in attention scale (2^-5, exact)
                *(uint32_t*)(HhU + i0) = pack_h2(v0 * SCALE_, v1 * SCALE_);
                *(uint32_t*)(HhU + i1) = pack_h2(v2 * SCALE_, v3 * SCALE_);
            } else {
                *(float2*)(C + i0) = make_float2(v0, v1);
                *(float2*)(C + i1) = make_float2(v2, v3);
            }
        }
    }
}

// ---------------------------------------------------------------------------
// Fused ReLU attention, fp16 2-term, 256 threads, 2 CTAs/SM.
// Warp qg (0-7) owns 16 q rows x full kv sweep; chunk = 64 kv rows, 32 chunks.
// No cross-warp reduction. Q is pre-scaled by 2^-5 in the Q projection.
// smem: Qh 16K | 3 x (Kh|Kl|Vh|Vl 8K each) = 112K -> 2 CTAs co-resident.
// ---------------------------------------------------------------------------
#define AKV(s) (16384 + (s) * 32768)
#define AKL 8192
#define AVH 16384
#define AVL 24576
#define SMEM_ATTN 114688

__device__ __forceinline__ void attn_load_kv(uint32_t base,
        const char* gK_h, const char* gK_l, const char* gV_h, const char* gV_l,
        int kc, int tid) {
    #pragma unroll
    for (int i = 0; i < 2; i++) {
        int idx = tid + i * 256;            // 0..511 : r 0..63, sg 0..7
        int r = idx >> 3, sg = idx & 7;
        uint32_t so = SMEM_SWIZZLE_128B((uint32_t)(r * 128 + sg * 16));
        size_t go = (size_t)(kc * 64 + r) * 2048 + sg * 16;
        cp16(base + so,       gK_h + go);
        cp16(base + AKL + so, gK_l + go);
        cp16(base + AVH + so, gV_h + go);
        cp16(base + AVL + so, gV_l + go);
    }
}

__global__ __launch_bounds__(256, 2)
void attn_mma(const __half* __restrict__ qh,
              const __half* __restrict__ kh, const __half* __restrict__ kl,
              const __half* __restrict__ vh, const __half* __restrict__ vl,
              __half* __restrict__ oh, __half* __restrict__ ol) {
    extern __shared__ char smem[];
    const uint32_t sb = smem_to_u32(smem);
    const int tid = threadIdx.x, lane = tid & 31, qg = tid >> 5;
    const int qt = blockIdx.x, h = blockIdx.y, b = blockIdx.z;
    const int q0 = qt * 128;
    const int g = lane >> 2, tg = lane & 3;

    const size_t hb = ((size_t)b * S_) * E_ + h * D_;
    const char* gQ_h = (const char*)(qh + hb);
    const char* gK_h = (const char*)(kh + hb);
    const char* gK_l = (const char*)(kl + hb);
    const char* gV_h = (const char*)(vh + hb);
    const char* gV_l = (const char*)(vl + hb);
    const unsigned* pm = g_pmask + (size_t)b * S_ * PW_;

    // prologue: group0 = Q + KV0, group1 = KV1
    #pragma unroll
    for (int i = 0; i < 4; i++) {
        int idx = tid + i * 256;            // 0..1023 : r 0..127
        int r = idx >> 3, sg = idx & 7;
        uint32_t so = SMEM_SWIZZLE_128B((uint32_t)(r * 128 + sg * 16));
        cp16(sb + so, gQ_h + (size_t)(q0 + r) * 2048 + sg * 16);
    }
    attn_load_kv(sb + AKV(0), gK_h, gK_l, gV_h, gV_l, 0, tid);
    CP_COMMIT();
    attn_load_kv(sb + AKV(1), gK_h, gK_l, gV_h, gV_l, 1, tid);
    CP_COMMIT();

    // fragment addressing
    const int arow = qg * 16 + (lane & 15);
    const uint32_t a_kb = (uint32_t)((lane >> 4) * 16);
    const uint32_t lxor = (uint32_t)((lane & 7) << 4);
    const int brow = (lane & 7) + ((lane >> 4) << 3);   // + p*16, kv row in chunk
    const uint32_t b_kb = (uint32_t)(((lane >> 3) & 1) * 16);
    const int vrow = lane & 15;                          // + j*16
    const uint32_t vdb = (uint32_t)((lane >> 4) * 16);
    const int r0 = q0 + qg * 16 + g;                     // thread's q rows: r0, r0+8

    uint32_t qfh[4][4];                                  // Q fragments, resident
    float c2[8][4];                                      // O accum (16q x 64d)
    #pragma unroll
    for (int j = 0; j < 8; j++)
        #pragma unroll
        for (int q = 0; q < 4; q++) c2[j][q] = 0.f;

    for (int kc = 0; kc < 32; kc++) {
        uint32_t kv = sb + AKV(kc % 3);
        if (kc < 31) CP_WAIT1(); else CP_WAIT0();
        __syncthreads();            // stage kc visible; all warps done with kc-1
        if (kc + 2 < 32) {
            attn_load_kv(sb + AKV((kc + 2) % 3), gK_h, gK_l, gV_h, gV_l, kc + 2, tid);
            CP_COMMIT();
        }
        if (kc == 0) {              // Q fragments (arrived with group0)
            #pragma unroll
            for (int kk = 0; kk < 4; kk++) {
                uint32_t ra = sb + (uint32_t)(arow * 128)
                                 + (((uint32_t)(kk * 32) + a_kb) ^ lxor);
                ldsm4(qfh[kk], ra);
            }
        }

        // ---- stage 1: S(16q x 64kv) = Qh @ (Kh + Kl)^T  (Q pre-scaled) ----
        float c1[8][4];
        #pragma unroll
        for (int j = 0; j < 8; j++)
            #pragma unroll
            for (int q = 0; q < 4; q++) c1[j][q] = 0.f;
        #pragma unroll
        for (int kk = 0; kk < 4; kk++) {
            #pragma unroll
            for (int p = 0; p < 4; p++) {
                uint32_t khf[4], klf[4];
                uint32_t rb = kv + (uint32_t)((brow + p * 16) * 128)
                                 + (((uint32_t)(kk * 32) + b_kb) ^ lxor);
                ldsm4(khf, rb);
                ldsm4(klf, rb + AKL);
                #pragma unroll
                for (int t = 0; t < 2; t++)
                    mma_f16(c1[p*2+t], qfh[kk], &khf[t*2]);
                #pragma unroll
                for (int t = 0; t < 2; t++)
                    mma_f16(c1[p*2+t], qfh[kk], &klf[t*2]);
            }
        }

        // ---- mask + relu (scale already folded into Q) ----
        {
            size_t mb = (size_t)r0 * PW_ + kc * 2;
            unsigned m0a = pm[mb],         m0b = pm[mb + 1];
            unsigned m1a = pm[mb + PW_*8], m1b = pm[mb + PW_*8 + 1];
            #pragma unroll
            for (int nt = 0; nt < 8; nt++) {
                int col = nt * 8 + 2 * tg;
                int bit = col & 31;
                unsigned w0 = (col < 32) ? m0a : m0b;
                unsigned w1 = (col < 32) ? m1a : m1b;
                c1[nt][0] = ((w0 >> bit) & 1u)       ? 0.f : fmaxf(c1[nt][0], 0.f);
                c1[nt][1] = ((w0 >> (bit + 1)) & 1u) ? 0.f : fmaxf(c1[nt][1], 0.f);
                c1[nt][2] = ((w1 >> bit) & 1u)       ? 0.f : fmaxf(c1[nt][2], 0.f);
                c1[nt][3] = ((w1 >> (bit + 1)) & 1u) ? 0.f : fmaxf(c1[nt][3], 0.f);
            }
        }

        // ---- stage 2: O += Sh @ (Vh + Vl) ----
        #pragma unroll
        for (int j = 0; j < 4; j++) {
            uint32_t sh[4];
            sh[0] = pack_h2(c1[2*j][0],   c1[2*j][1]);
            sh[1] = pack_h2(c1[2*j][2],   c1[2*j][3]);
            sh[2] = pack_h2(c1[2*j+1][0], c1[2*j+1][1]);
            sh[3] = pack_h2(c1[2*j+1][2], c1[2*j+1][3]);
            #pragma unroll
            for (int p = 0; p < 4; p++) {
                uint32_t vhf[4], vlf[4];
                uint32_t off = (uint32_t)((vrow + j * 16) * 128) + (uint32_t)(p * 32) + vdb;
                uint32_t rb = kv + AVH + SMEM_SWIZZLE_128B(off);
                ldsm4t(vhf, rb);
                ldsm4t(vlf, rb + AKL);
                #pragma unroll
                for (int t = 0; t < 2; t++)
                    mma_f16(c2[p*2+t], sh, &vhf[t*2]);
                #pragma unroll
                for (int t = 0; t < 2; t++)
                    mma_f16(c2[p*2+t], sh, &vlf[t*2]);
            }
        }
    }

    // ---- epilogue: warp owns its rows completely, direct write ----
    #pragma unroll
    for (int nt = 0; nt < 8; nt++) {
        int cidx = nt * 8 + 2 * tg;
        size_t i0 = ((size_t)b * S_ + r0) * E_ + h * D_ + cidx;
        size_t i1 = i0 + (size_t)8 * E_;
        uint32_t h01, l01, h23, l23;
        split2h(c2[nt][0], c2[nt][1], h01, l01);
        split2h(c2[nt][2], c2[nt][3], h23, l23);
        *(uint32_t*)(oh + i0) = h01; *(uint32_t*)(ol + i0) = l01;
        *(uint32_t*)(oh + i1) = h23; *(uint32_t*)(ol + i1) = l23;
    }
}

// ---------------------------------------------------------------------------
// out = LayerNorm(a + res)*gamma + beta ; also writes fp16 hi/lo of out.
// Two rows per CTA: 256 threads, 128/row, 8 floats/thread.
// ---------------------------------------------------------------------------
__global__ __launch_bounds__(256)
void add_ln_kernel(const float* __restrict__ a, const float* __restrict__ res,
                   const float* __restrict__ gamma, const float* __restrict__ beta,
                   float* __restrict__ out,
                   __half* __restrict__ oh, __half* __restrict__ ol) {
    __shared__ float red[8];
    __shared__ float bcast[2];
    const int tid = threadIdx.x;
    const int half = tid >> 7, t = tid & 127;
    const int row = blockIdx.x * 2 + half;
    const int lane = tid & 31, wid = tid >> 5;     // wids 0-3 row0, 4-7 row1
    const float* ap = a + (size_t)row * E_ + t * 8;
    const float* xp = res + (size_t)row * E_ + t * 8;
    float4 va0 = *(const float4*)ap,       vx0 = *(const float4*)xp;
    float4 va1 = *(const float4*)(ap + 4), vx1 = *(const float4*)(xp + 4);
    float v[8];
    v[0] = va0.x + vx0.x; v[1] = va0.y + vx0.y; v[2] = va0.z + vx0.z; v[3] = va0.w + vx0.w;
    v[4] = va1.x + vx1.x; v[5] = va1.y + vx1.y; v[6] = va1.z + vx1.z; v[7] = va1.w + vx1.w;
    float s = 0.f;
    #pragma unroll
    for (int i = 0; i < 8; i++) s += v[i];
    #pragma unroll
    for (int off = 16; off > 0; off >>= 1) s += __shfl_xor_sync(~0u, s, off);
    if (lane == 0) red[wid] = s;
    __syncthreads();
    if (t == 0) {
        float tt = 0.f;
        #pragma unroll
        for (int i = 0; i < 4; i++) tt += red[half * 4 + i];
        bcast[half] = tt;
    }
    __syncthreads();
    float mean = bcast[half] * (1.0f / E_);
    float d[8], vs = 0.f;
    #pragma unroll
    for (int i = 0; i < 8; i++) { d[i] = v[i] - mean; vs += d[i] * d[i]; }
    #pragma unroll
    for (int off = 16; off > 0; off >>= 1) vs += __shfl_xor_sync(~0u, vs, off);
    __syncthreads();
    if (lane == 0) red[wid] = vs;
    __syncthreads();
    if (t == 0) {
        float tt = 0.f;
        #pragma unroll
        for (int i = 0; i < 4; i++) tt += red[half * 4 + i];
        bcast[half] = tt;
    }
    __syncthreads();
    float inv = rsqrtf(bcast[half] * (1.0f / E_) + EPS_);
    float o[8];
    #pragma unroll
    for (int i = 0; i < 8; i += 4) {
        float4 gq = *(const float4*)(gamma + t * 8 + i);
        float4 bt = *(const float4*)(beta + t * 8 + i);
        o[i]   = d[i]   * inv * gq.x + bt.x;
        o[i+1] = d[i+1] * inv * gq.y + bt.y;
        o[i+2] = d[i+2] * inv * gq.z + bt.z;
        o[i+3] = d[i+3] * inv * gq.w + bt.w;
    }
    size_t i0 = (size_t)row * E_ + t * 8;
    *(float4*)(out + i0)     = make_float4(o[0], o[1], o[2], o[3]);
    *(float4*)(out + i0 + 4) = make_float4(o[4], o[5], o[6], o[7]);
    uint32_t h01, l01, h23, l23, h45, l45, h67, l67;
    split2h(o[0], o[1], h01, l01);
    split2h(o[2], o[3], h23, l23);
    split2h(o[4], o[5], h45, l45);
    split2h(o[6], o[7], h67, l67);
    *(uint4*)(oh + i0) = make_uint4(h01, h23, h45, h67);
    *(uint4*)(ol + i0) = make_uint4(l01, l23, l45, l67);
}

// ---------------------------------------------------------------------------
extern "C" void kernel_launch(void* const* d_in, const int* in_sizes, int n_in,
                              void* d_out, int out_size) {
    const float* query = (const float*)d_in[0];
    const float* value = (const float*)d_in[1];
    const int*   mask  = (const int*)d_in[2];
    const float* Wq = (const float*)d_in[3];
    const float* Wk = (const float*)d_in[4];
    const float* Wv = (const float*)d_in[5];
    const float* Wo = (const float*)d_in[6];
    const float* bq = (const float*)d_in[7];
    const float* bk = (const float*)d_in[8];
    const float* bv = (const float*)d_in[9];
    const float* bo = (const float*)d_in[10];
    const float* gamma = (const float*)d_in[11];
    const float* beta  = (const float*)d_in[12];
    float* out = (float*)d_out;

    float *x, *proj;
    cudaGetSymbolAddress((void**)&x,    g_x);
    cudaGetSymbolAddress((void**)&proj, g_proj);
    __half *xh, *xl, *ath, *atl, *vih, *vil, *wh;
    __half *qh, *kh, *kl, *vh, *vl;
    cudaGetSymbolAddress((void**)&xh, g_xh);   cudaGetSymbolAddress((void**)&xl, g_xl);
    cudaGetSymbolAddress((void**)&qh, g_qh);
    cudaGetSymbolAddress((void**)&kh, g_kh);   cudaGetSymbolAddress((void**)&kl, g_kl);
    cudaGetSymbolAddress((void**)&vh, g_vh);   cudaGetSymbolAddress((void**)&vl, g_vl);
    cudaGetSymbolAddress((void**)&ath, g_ath); cudaGetSymbolAddress((void**)&atl, g_atl);
    cudaGetSymbolAddress((void**)&vih, g_vih); cudaGetSymbolAddress((void**)&vil, g_vil);
    cudaGetSymbolAddress((void**)&wh, g_wh);

    cudaFuncSetAttribute(gemm_mma<0>, cudaFuncAttributeMaxDynamicSharedMemorySize, 2 * GSTAGE);
    cudaFuncSetAttribute(gemm_mma<2>, cudaFuncAttributeMaxDynamicSharedMemorySize, 2 * GSTAGE);
    cudaFuncSetAttribute(gemm_mma<3>, cudaFuncAttributeMaxDynamicSharedMemorySize, 2 * GSTAGE);
    cudaFuncSetAttribute(attn_mma, cudaFuncAttributeMaxDynamicSharedMemorySize, SMEM_ATTN);

    // fused setup: mask pack + activation splits + weight split/transpose
    setup_fused<<<SETUP_GRID, 256>>>(mask, query, value, Wq, Wk, Wv, Wo,
                                     xh, xl, vih, vil, wh);

    // mega K/V projection: all layers, one launch
    dim3 megagrid(16 * L_, 32);     // 2048 CTAs
    gemm_mma<3><<<megagrid, 512, 2*GSTAGE>>>(vih, vil, wh, bk, bv, nullptr,
                                             kh, kl, vh, vl);

    dim3 qgrid(8, 32);              // 256 CTAs
    dim3 agrid(S_/128, H_, B_);     // 1024 CTAs, 2/SM
    const size_t kvstride = (size_t)M_ * E_;
    for (int l = 0; l < L_; l++) {
        size_t w0 = ((size_t)(l*4 + 0)) << 20;
        size_t w3 = ((size_t)(l*4 + 3)) << 20;
        gemm_mma<2><<<qgrid, 512, 2*GSTAGE>>>(xh, xl, wh + w0,
                                              bq + l*E_, nullptr, nullptr,
                                              qh, nullptr, nullptr, nullptr);
        attn_mma<<<agrid, 256, SMEM_ATTN>>>(qh,
                                            kh + l*kvstride, kl + l*kvstride,
                                            vh + l*kvstride, vl + l*kvstride,
                                            ath, atl);
        gemm_mma<0><<<qgrid, 512, 2*GSTAGE>>>(ath, atl, wh + w3,
                                              bo + l*E_, nullptr, proj,
                                              nullptr, nullptr, nullptr, nullptr);
        add_ln_kernel<<<M_/2, 256>>>(proj, (l == 0) ? query : x,
                                     gamma + l*E_, beta + l*E_,
                                     (l == L_-1) ? out : x, xh, xl);
    }
}

// round 17
// speedup vs baseline: 1.1039x; 1.0554x over previous
#include <cuda_runtime.h>
#include <cuda_fp16.h>
#include <cstdint>

#define B_ 4
#define S_ 2048
#define E_ 1024
#define H_ 16
#define D_ 64
#define L_ 4
#define M_ (B_*S_)          // 8192 rows
#define PW_ (S_/32)         // 64 mask words per row
#define SCALE_ 0.03125f     // E^-0.5 = 2^-5 (exact in fp16; folded into Q proj)
#define EPS_ 1e-5f

// ---------------- scratch (__device__ globals: allocation-free rule) -------
__device__ float g_x[M_*E_];
__device__ float g_proj[M_*E_];
__device__ unsigned g_pmask[B_*S_*PW_];
__device__ __half g_xh[M_*E_],  g_xl[M_*E_];
__device__ __half g_qh[M_*E_];
__device__ __half g_kh[L_*M_*E_], g_kl[L_*M_*E_];   // all layers (value is layer-invariant)
__device__ __half g_vh[L_*M_*E_], g_vl[L_*M_*E_];
__device__ __half g_ath[M_*E_], g_atl[M_*E_];
__device__ __half g_vih[M_*E_], g_vil[M_*E_];
__device__ __half g_wh[L_*4*E_*E_];   // weights [N][K] (transposed), fp16

// ============================ portable PTX helpers ==========================
__device__ __forceinline__ uint32_t smem_to_u32(const void* p) {
    uint32_t a;
    asm("{ .reg .u64 t; cvta.to.shared.u64 t, %1; cvt.u32.u64 %0, t; }"
        : "=r"(a) : "l"(p));
    return a;
}
#define SMEM_SWIZZLE_128B(o) ((o) ^ (((o) >> 3) & 0x70))

__device__ __forceinline__ void cp16(uint32_t dst, const void* src) {
    asm volatile("cp.async.cg.shared.global [%0], [%1], 16;" :: "r"(dst), "l"(src) : "memory");
}
#define CP_COMMIT() asm volatile("cp.async.commit_group;" ::: "memory")
#define CP_WAIT0()  asm volatile("cp.async.wait_group 0;" ::: "memory")
#define CP_WAIT1()  asm volatile("cp.async.wait_group 1;" ::: "memory")

__device__ __forceinline__ void ldsm4(uint32_t* r, uint32_t a) {
    asm volatile("ldmatrix.sync.aligned.m8n8.x4.shared.b16 {%0,%1,%2,%3}, [%4];"
        : "=r"(r[0]), "=r"(r[1]), "=r"(r[2]), "=r"(r[3]) : "r"(a));
}
__device__ __forceinline__ void ldsm4t(uint32_t* r, uint32_t a) {
    asm volatile("ldmatrix.sync.aligned.m8n8.x4.trans.shared.b16 {%0,%1,%2,%3}, [%4];"
        : "=r"(r[0]), "=r"(r[1]), "=r"(r[2]), "=r"(r[3]) : "r"(a));
}
// D += A(16x16) * B(16x8), fp16 in, fp32 accum
__device__ __forceinline__ void mma_f16(float* c, const uint32_t* a, const uint32_t* b) {
    asm volatile("mma.sync.aligned.m16n8k16.row.col.f32.f16.f16.f32 "
        "{%0,%1,%2,%3}, {%4,%5,%6,%7}, {%8,%9}, {%0,%1,%2,%3};"
        : "+f"(c[0]), "+f"(c[1]), "+f"(c[2]), "+f"(c[3])
        : "r"(a[0]), "r"(a[1]), "r"(a[2]), "r"(a[3]), "r"(b[0]), "r"(b[1]));
}
__device__ __forceinline__ void split2h(float v0, float v1, uint32_t& hi, uint32_t& lo) {
    __half2 h = __floats2half2_rn(v0, v1);
    float2 hf = __half22float2(h);
    __half2 l = __floats2half2_rn(v0 - hf.x, v1 - hf.y);
    hi = *(uint32_t*)&h; lo = *(uint32_t*)&l;
}
__device__ __forceinline__ uint32_t pack_h2(float v0, float v1) {
    __half2 h = __floats2half2_rn(v0, v1);
    return *(uint32_t*)&h;
}

// ---------------------------------------------------------------------------
// Fused setup: pack_mask + split_act(query) + split_act(value) + weight
// split/transpose, one launch. Segments decoded from blockIdx.x.
// ---------------------------------------------------------------------------
#define SETUP_GRID 49152

__global__ __launch_bounds__(256)
void setup_fused(const int* __restrict__ mask,
                 const float* __restrict__ query, const float* __restrict__ value,
                 const float* __restrict__ Wq, const float* __restrict__ Wk,
                 const float* __restrict__ Wv, const float* __restrict__ Wo,
                 __half* __restrict__ xh, __half* __restrict__ xl,
                 __half* __restrict__ vih, __half* __restrict__ vil,
                 __half* __restrict__ whbase) {
    __shared__ float t[32][33];
    const int bid = blockIdx.x, tid = threadIdx.x;
    if (bid < 16384) {                       // ---- pack mask ----
        #pragma unroll
        for (int j = 0; j < 4; j++) {
            unsigned i = (unsigned)bid * 1024u + j * 256u + tid;
            unsigned word = __ballot_sync(0xffffffffu, mask[i] == 1);
            if ((tid & 31) == 0) g_pmask[i >> 5] = word;
        }
    } else if (bid < 32768) {                // ---- split activations ----
        int vb = bid - 16384;
        const float* src = (vb < 8192) ? query : value;
        __half* hi = (vb < 8192) ? xh : vih;
        __half* lo = (vb < 8192) ? xl : vil;
        size_t i = (size_t)(vb & 8191) * 256 + tid;
        float4 v = ((const float4*)src)[i];
        uint32_t h01, l01, h23, l23;
        split2h(v.x, v.y, h01, l01);
        split2h(v.z, v.w, h23, l23);
        ((uint2*)hi)[i] = make_uint2(h01, h23);
        ((uint2*)lo)[i] = make_uint2(l01, l23);
    } else {                                 // ---- weight split/transpose ----
        int vb = bid - 32768;
        int z = vb >> 10, slot = z & 3, layer = z >> 2;
        const float* Wb = (slot == 0) ? Wq : (slot == 1) ? Wk : (slot == 2) ? Wv : Wo;
        const float* W = Wb + (size_t)layer * E_ * E_;
        __half* hi = whbase + ((size_t)z << 20);
        int bn = (vb & 31) * 32, bk = ((vb >> 5) & 31) * 32;
        int tx = tid & 31, ty = tid >> 5;
        #pragma unroll
        for (int i = 0; i < 32; i += 8)
            t[ty + i][tx] = W[(size_t)(bk + ty + i) * E_ + bn + tx];
        __syncthreads();
        #pragma unroll
        for (int i = 0; i < 32; i += 8)
            hi[(size_t)(bn + ty + i) * E_ + bk + tx] = __float2half(t[tx][ty + i]);
    }
}

// ---------------------------------------------------------------------------
// fp16x2 MMA GEMM: C = (Ah+Al) @ Wh^T + bias. CTA tile 128x128, 256 threads,
// warp tile 32x64, K-chunk 64, double-buffered cp.async, 2 CTAs/SM.
// MODE 0: fp32 out. MODE 2: fp16 hi only, PRESCALED by SCALE_ (Q projection).
// MODE 3: mega K/V — bn decodes (layer, K-or-V, col-block); fp16 hi/lo out.
// smem stage: Ah 16K | Al 16K | W 16K = 48K; x2 stages = 96K -> 2 CTAs/SM.
// ---------------------------------------------------------------------------
#define GS_AL 16384
#define GS_W  32768
#define GSTAGE 49152

__device__ __forceinline__ void gemm_load_stage(uint32_t base,
        const char* gA_h, const char* gA_l, const char* gW,
        int kc, int tid) {
    size_t co = (size_t)kc * 128;
    #pragma unroll
    for (int i = 0; i < 4; i++) {           // A: 128 rows x 8 seg, hi+lo
        int idx = tid + i * 256;
        int r = idx >> 3, sg = idx & 7;
        uint32_t so = SMEM_SWIZZLE_128B((uint32_t)(r * 128 + sg * 16));
        size_t go = (size_t)r * 2048 + co + sg * 16;
        cp16(base + so, gA_h + go);
        cp16(base + GS_AL + so, gA_l + go);
    }
    #pragma unroll
    for (int i = 0; i < 4; i++) {           // W: 128 rows x 8 seg
        int idx = tid + i * 256;
        int r = idx >> 3, sg = idx & 7;
        uint32_t so = SMEM_SWIZZLE_128B((uint32_t)(r * 128 + sg * 16));
        cp16(base + GS_W + so, gW + (size_t)r * 2048 + co + sg * 16);
    }
}

template<int MODE>
__global__ __launch_bounds__(256, 2)
void gemm_mma(const __half* __restrict__ Ah, const __half* __restrict__ Al,
              const __half* __restrict__ Wh,
              const float* __restrict__ bias, const float* __restrict__ bias2,
              float* __restrict__ C,
              __half* __restrict__ Hh, __half* __restrict__ Hl,
              __half* __restrict__ Hh2, __half* __restrict__ Hl2) {
    extern __shared__ char smem[];
    const uint32_t sb = smem_to_u32(smem);
    const int tid = threadIdx.x, lane = tid & 31, w = tid >> 5;
    const int bm = blockIdx.y, bn = blockIdx.x;
    const int m0 = (w & 3) * 32, n0 = (w >> 2) * 64;

    const char* gA_h = (const char*)(Ah + (size_t)bm * 128 * E_);
    const char* gA_l = (const char*)(Al + (size_t)bm * 128 * E_);
    const char* gW;
    const float* bias_sel = bias;
    __half *HhU = Hh, *HlU = Hl;
    int colbase;
    if (MODE == 3) {
        int layer = bn >> 4, sub = bn & 15;
        int slot = sub >> 3, wcol = sub & 7;
        gW = (const char*)(Wh + (((size_t)(layer * 4 + 1 + slot)) << 20)
                              + (size_t)wcol * 128 * E_);
        bias_sel = (slot ? bias2 : bias) + layer * E_;
        HhU = (slot ? Hh2 : Hh) + (size_t)layer * ((size_t)M_ * E_);
        HlU = (slot ? Hl2 : Hl) + (size_t)layer * ((size_t)M_ * E_);
        colbase = wcol * 128;
    } else {
        gW = (const char*)(Wh + (size_t)bn * 128 * E_);
        colbase = bn * 128;
    }

    const int arow = m0 + (lane & 15);
    const uint32_t a_kb = (uint32_t)((lane >> 4) * 16);
    const uint32_t axor = (uint32_t)((arow & 7) << 4);
    const int brow = n0 + (lane & 7) + ((lane >> 4) << 3);
    const uint32_t b_kb = (uint32_t)(((lane >> 3) & 1) * 16);
    const uint32_t bxor = (uint32_t)((brow & 7) << 4);

    float c[2][8][4];
    #pragma unroll
    for (int i = 0; i < 2; i++)
        #pragma unroll
        for (int j = 0; j < 8; j++)
            #pragma unroll
            for (int q = 0; q < 4; q++) c[i][j][q] = 0.f;

    gemm_load_stage(sb, gA_h, gA_l, gW, 0, tid);
    CP_COMMIT();

    for (int kc = 0; kc < 16; kc++) {
        uint32_t stg = sb + (uint32_t)((kc & 1) * GSTAGE);
        CP_WAIT0();
        __syncthreads();            // stage kc visible; all warps done with kc-1
        if (kc + 1 < 16) {
            gemm_load_stage(sb + (uint32_t)(((kc + 1) & 1) * GSTAGE),
                            gA_h, gA_l, gW, kc + 1, tid);
            CP_COMMIT();
        }
        #pragma unroll
        for (int kk = 0; kk < 4; kk++) {
            uint32_t ah[2][4], al[2][4], bh[4][4];
            #pragma unroll
            for (int mt = 0; mt < 2; mt++) {
                uint32_t ra = stg + (uint32_t)((arow + mt * 16) * 128)
                                  + (((uint32_t)(kk * 32) + a_kb) ^ axor);
                ldsm4(ah[mt], ra);
                ldsm4(al[mt], ra + GS_AL);
            }
            #pragma unroll
            for (int p = 0; p < 4; p++) {
                uint32_t rb = stg + GS_W + (uint32_t)((brow + p * 16) * 128)
                                  + (((uint32_t)(kk * 32) + b_kb) ^ bxor);
                ldsm4(bh[p], rb);
            }
            #pragma unroll
            for (int mt = 0; mt < 2; mt++)
                #pragma unroll
                for (int p = 0; p < 4; p++)
                    #pragma unroll
                    for (int t = 0; t < 2; t++)
                        mma_f16(c[mt][p*2+t], ah[mt], &bh[p][t*2]);
            #pragma unroll
            for (int mt = 0; mt < 2; mt++)
                #pragma unroll
                for (int p = 0; p < 4; p++)
                    #pragma unroll
                    for (int t = 0; t < 2; t++)
                        mma_f16(c[mt][p*2+t], al[mt], &bh[p][t*2]);
        }
    }

    // epilogue
    const int g = lane >> 2, tg = lane & 3;
    #pragma unroll
    for (int nt = 0; nt < 8; nt++) {
        int col = colbase + n0 + nt * 8 + 2 * tg;
        float b0 = bias_sel[col], b1 = bias_sel[col + 1];
        #pragma unroll
        for (int mt = 0; mt < 2; mt++) {
            int row = bm * 128 + m0 + mt * 16 + g;
            float v0 = c[mt][nt][0] + b0, v1 = c[mt][nt][1] + b1;
            float v2 = c[mt][nt][2] + b0, v3 = c[mt][nt][3] + b1;
            size_t i0 = (size_t)row * E_ + col;
            size_t i1 = i0 + (size_t)8 * E_;
            if (MODE == 3) {
                uint32_t h01, l01, h23, l23;
                split2h(v0, v1, h01, l01);
                split2h(v2, v3, h23, l23);
                *(uint32_t*)(HhU + i0) = h01; *(uint32_t*)(HlU + i0) = l01;
                *(uint32_t*)(HhU + i1) = h23; *(uint32_t*)(HlU + i1) = l23;
            } else if (MODE == 2) {    // Q projection: fold in attention scale (2^-5, exact)
                *(uint32_t*)(HhU + i0) = pack_h2(v0 * SCALE_, v1 * SCALE_);
                *(uint32_t*)(HhU + i1) = pack_h2(v2 * SCALE_, v3 * SCALE_);
            } else {
                *(float2*)(C + i0) = make_float2(v0, v1);
                *(float2*)(C + i1) = make_float2(v2, v3);
            }
        }
    }
}

// ---------------------------------------------------------------------------
// Fused ReLU attention, fp16 2-term, 256 threads, 2 CTAs/SM.
// Warp qg (0-7) owns 16 q rows x full kv sweep; chunk = 64 kv rows, 32 chunks.
// No cross-warp reduction. Q is pre-scaled by 2^-5 in the Q projection.
// smem: Qh 16K | 3 x (Kh|Kl|Vh|Vl 8K each) = 112K -> 2 CTAs co-resident.
// ---------------------------------------------------------------------------
#define AKV(s) (16384 + (s) * 32768)
#define AKL 8192
#define AVH 16384
#define AVL 24576
#define SMEM_ATTN 114688

__device__ __forceinline__ void attn_load_kv(uint32_t base,
        const char* gK_h, const char* gK_l, const char* gV_h, const char* gV_l,
        int kc, int tid) {
    #pragma unroll
    for (int i = 0; i < 2; i++) {
        int idx = tid + i * 256;            // 0..511 : r 0..63, sg 0..7
        int r = idx >> 3, sg = idx & 7;
        uint32_t so = SMEM_SWIZZLE_128B((uint32_t)(r * 128 + sg * 16));
        size_t go = (size_t)(kc * 64 + r) * 2048 + sg * 16;
        cp16(base + so,       gK_h + go);
        cp16(base + AKL + so, gK_l + go);
        cp16(base + AVH + so, gV_h + go);
        cp16(base + AVL + so, gV_l + go);
    }
}

__global__ __launch_bounds__(256, 2)
void attn_mma(const __half* __restrict__ qh,
              const __half* __restrict__ kh, const __half* __restrict__ kl,
              const __half* __restrict__ vh, const __half* __restrict__ vl,
              __half* __restrict__ oh, __half* __restrict__ ol) {
    extern __shared__ char smem[];
    const uint32_t sb = smem_to_u32(smem);
    const int tid = threadIdx.x, lane = tid & 31, qg = tid >> 5;
    const int qt = blockIdx.x, h = blockIdx.y, b = blockIdx.z;
    const int q0 = qt * 128;
    const int g = lane >> 2, tg = lane & 3;

    const size_t hb = ((size_t)b * S_) * E_ + h * D_;
    const char* gQ_h = (const char*)(qh + hb);
    const char* gK_h = (const char*)(kh + hb);
    const char* gK_l = (const char*)(kl + hb);
    const char* gV_h = (const char*)(vh + hb);
    const char* gV_l = (const char*)(vl + hb);
    const unsigned* pm = g_pmask + (size_t)b * S_ * PW_;

    // prologue: group0 = Q + KV0, group1 = KV1
    #pragma unroll
    for (int i = 0; i < 4; i++) {
        int idx = tid + i * 256;            // 0..1023 : r 0..127
        int r = idx >> 3, sg = idx & 7;
        uint32_t so = SMEM_SWIZZLE_128B((uint32_t)(r * 128 + sg * 16));
        cp16(sb + so, gQ_h + (size_t)(q0 + r) * 2048 + sg * 16);
    }
    attn_load_kv(sb + AKV(0), gK_h, gK_l, gV_h, gV_l, 0, tid);
    CP_COMMIT();
    attn_load_kv(sb + AKV(1), gK_h, gK_l, gV_h, gV_l, 1, tid);
    CP_COMMIT();

    // fragment addressing
    const int arow = qg * 16 + (lane & 15);
    const uint32_t a_kb = (uint32_t)((lane >> 4) * 16);
    const uint32_t lxor = (uint32_t)((lane & 7) << 4);
    const int brow = (lane & 7) + ((lane >> 4) << 3);   // + p*16, kv row in chunk
    const uint32_t b_kb = (uint32_t)(((lane >> 3) & 1) * 16);
    const int vrow = lane & 15;                          // + j*16
    const uint32_t vdb = (uint32_t)((lane >> 4) * 16);
    const int r0 = q0 + qg * 16 + g;                     // thread's q rows: r0, r0+8

    uint32_t qfh[4][4];                                  // Q fragments, resident
    float c2[8][4];                                      // O accum (16q x 64d)
    #pragma unroll
    for (int j = 0; j < 8; j++)
        #pragma unroll
        for (int q = 0; q < 4; q++) c2[j][q] = 0.f;

    for (int kc = 0; kc < 32; kc++) {
        uint32_t kv = sb + AKV(kc % 3);
        if (kc < 31) CP_WAIT1(); else CP_WAIT0();
        __syncthreads();            // stage kc visible; all warps done with kc-1
        if (kc + 2 < 32) {
            attn_load_kv(sb + AKV((kc + 2) % 3), gK_h, gK_l, gV_h, gV_l, kc + 2, tid);
            CP_COMMIT();
        }
        if (kc == 0) {              // Q fragments (arrived with group0)
            #pragma unroll
            for (int kk = 0; kk < 4; kk++) {
                uint32_t ra = sb + (uint32_t)(arow * 128)
                                 + (((uint32_t)(kk * 32) + a_kb) ^ lxor);
                ldsm4(qfh[kk], ra);
            }
        }

        // ---- stage 1: S(16q x 64kv) = Qh @ (Kh + Kl)^T  (Q pre-scaled) ----
        float c1[8][4];
        #pragma unroll
        for (int j = 0; j < 8; j++)
            #pragma unroll
            for (int q = 0; q < 4; q++) c1[j][q] = 0.f;
        #pragma unroll
        for (int kk = 0; kk < 4; kk++) {
            #pragma unroll
            for (int p = 0; p < 4; p++) {
                uint32_t khf[4], klf[4];
                uint32_t rb = kv + (uint32_t)((brow + p * 16) * 128)
                                 + (((uint32_t)(kk * 32) + b_kb) ^ lxor);
                ldsm4(khf, rb);
                ldsm4(klf, rb + AKL);
                #pragma unroll
                for (int t = 0; t < 2; t++)
                    mma_f16(c1[p*2+t], qfh[kk], &khf[t*2]);
                #pragma unroll
                for (int t = 0; t < 2; t++)
                    mma_f16(c1[p*2+t], qfh[kk], &klf[t*2]);
            }
        }

        // ---- mask + relu (scale already folded into Q) ----
        {
            size_t mb = (size_t)r0 * PW_ + kc * 2;
            unsigned m0a = pm[mb],         m0b = pm[mb + 1];
            unsigned m1a = pm[mb + PW_*8], m1b = pm[mb + PW_*8 + 1];
            #pragma unroll
            for (int nt = 0; nt < 8; nt++) {
                int col = nt * 8 + 2 * tg;
                int bit = col & 31;
                unsigned w0 = (col < 32) ? m0a : m0b;
                unsigned w1 = (col < 32) ? m1a : m1b;
                c1[nt][0] = ((w0 >> bit) & 1u)       ? 0.f : fmaxf(c1[nt][0], 0.f);
                c1[nt][1] = ((w0 >> (bit + 1)) & 1u) ? 0.f : fmaxf(c1[nt][1], 0.f);
                c1[nt][2] = ((w1 >> bit) & 1u)       ? 0.f : fmaxf(c1[nt][2], 0.f);
                c1[nt][3] = ((w1 >> (bit + 1)) & 1u) ? 0.f : fmaxf(c1[nt][3], 0.f);
            }
        }

        // ---- stage 2: O += Sh @ (Vh + Vl) ----
        #pragma unroll
        for (int j = 0; j < 4; j++) {
            uint32_t sh[4];
            sh[0] = pack_h2(c1[2*j][0],   c1[2*j][1]);
            sh[1] = pack_h2(c1[2*j][2],   c1[2*j][3]);
            sh[2] = pack_h2(c1[2*j+1][0], c1[2*j+1][1]);
            sh[3] = pack_h2(c1[2*j+1][2], c1[2*j+1][3]);
            #pragma unroll
            for (int p = 0; p < 4; p++) {
                uint32_t vhf[4], vlf[4];
                uint32_t off = (uint32_t)((vrow + j * 16) * 128) + (uint32_t)(p * 32) + vdb;
                uint32_t rb = kv + AVH + SMEM_SWIZZLE_128B(off);
                ldsm4t(vhf, rb);
                ldsm4t(vlf, rb + AKL);
                #pragma unroll
                for (int t = 0; t < 2; t++)
                    mma_f16(c2[p*2+t], sh, &vhf[t*2]);
                #pragma unroll
                for (int t = 0; t < 2; t++)
                    mma_f16(c2[p*2+t], sh, &vlf[t*2]);
            }
        }
    }

    // ---- epilogue: warp owns its rows completely, direct write ----
    #pragma unroll
    for (int nt = 0; nt < 8; nt++) {
        int cidx = nt * 8 + 2 * tg;
        size_t i0 = ((size_t)b * S_ + r0) * E_ + h * D_ + cidx;
        size_t i1 = i0 + (size_t)8 * E_;
        uint32_t h01, l01, h23, l23;
        split2h(c2[nt][0], c2[nt][1], h01, l01);
        split2h(c2[nt][2], c2[nt][3], h23, l23);
        *(uint32_t*)(oh + i0) = h01; *(uint32_t*)(ol + i0) = l01;
        *(uint32_t*)(oh + i1) = h23; *(uint32_t*)(ol + i1) = l23;
    }
}

// ---------------------------------------------------------------------------
// out = LayerNorm(a + res)*gamma + beta ; also writes fp16 hi/lo of out.
// Two rows per CTA: 256 threads, 128/row, 8 floats/thread.
// ---------------------------------------------------------------------------
__global__ __launch_bounds__(256)
void add_ln_kernel(const float* __restrict__ a, const float* __restrict__ res,
                   const float* __restrict__ gamma, const float* __restrict__ beta,
                   float* __restrict__ out,
                   __half* __restrict__ oh, __half* __restrict__ ol) {
    __shared__ float red[8];
    __shared__ float bcast[2];
    const int tid = threadIdx.x;
    const int half = tid >> 7, t = tid & 127;
    const int row = blockIdx.x * 2 + half;
    const int lane = tid & 31, wid = tid >> 5;     // wids 0-3 row0, 4-7 row1
    const float* ap = a + (size_t)row * E_ + t * 8;
    const float* xp = res + (size_t)row * E_ + t * 8;
    float4 va0 = *(const float4*)ap,       vx0 = *(const float4*)xp;
    float4 va1 = *(const float4*)(ap + 4), vx1 = *(const float4*)(xp + 4);
    float v[8];
    v[0] = va0.x + vx0.x; v[1] = va0.y + vx0.y; v[2] = va0.z + vx0.z; v[3] = va0.w + vx0.w;
    v[4] = va1.x + vx1.x; v[5] = va1.y + vx1.y; v[6] = va1.z + vx1.z; v[7] = va1.w + vx1.w;
    float s = 0.f;
    #pragma unroll
    for (int i = 0; i < 8; i++) s += v[i];
    #pragma unroll
    for (int off = 16; off > 0; off >>= 1) s += __shfl_xor_sync(~0u, s, off);
    if (lane == 0) red[wid] = s;
    __syncthreads();
    if (t == 0) {
        float tt = 0.f;
        #pragma unroll
        for (int i = 0; i < 4; i++) tt += red[half * 4 + i];
        bcast[half] = tt;
    }
    __syncthreads();
    float mean = bcast[half] * (1.0f / E_);
    float d[8], vs = 0.f;
    #pragma unroll
    for (int i = 0; i < 8; i++) { d[i] = v[i] - mean; vs += d[i] * d[i]; }
    #pragma unroll
    for (int off = 16; off > 0; off >>= 1) vs += __shfl_xor_sync(~0u, vs, off);
    __syncthreads();
    if (lane == 0) red[wid] = vs;
    __syncthreads();
    if (t == 0) {
        float tt = 0.f;
        #pragma unroll
        for (int i = 0; i < 4; i++) tt += red[half * 4 + i];
        bcast[half] = tt;
    }
    __syncthreads();
    float inv = rsqrtf(bcast[half] * (1.0f / E_) + EPS_);
    float o[8];
    #pragma unroll
    for (int i = 0; i < 8; i += 4) {
        float4 gq = *(const float4*)(gamma + t * 8 + i);
        float4 bt = *(const float4*)(beta + t * 8 + i);
        o[i]   = d[i]   * inv * gq.x + bt.x;
        o[i+1] = d[i+1] * inv * gq.y + bt.y;
        o[i+2] = d[i+2] * inv * gq.z + bt.z;
        o[i+3] = d[i+3] * inv * gq.w + bt.w;
    }
    size_t i0 = (size_t)row * E_ + t * 8;
    *(float4*)(out + i0)     = make_float4(o[0], o[1], o[2], o[3]);
    *(float4*)(out + i0 + 4) = make_float4(o[4], o[5], o[6], o[7]);
    uint32_t h01, l01, h23, l23, h45, l45, h67, l67;
    split2h(o[0], o[1], h01, l01);
    split2h(o[2], o[3], h23, l23);
    split2h(o[4], o[5], h45, l45);
    split2h(o[6], o[7], h67, l67);
    *(uint4*)(oh + i0) = make_uint4(h01, h23, h45, h67);
    *(uint4*)(ol + i0) = make_uint4(l01, l23, l45, l67);
}

// ---------------------------------------------------------------------------
extern "C" void kernel_launch(void* const* d_in, const int* in_sizes, int n_in,
                              void* d_out, int out_size) {
    const float* query = (const float*)d_in[0];
    const float* value = (const float*)d_in[1];
    const int*   mask  = (const int*)d_in[2];
    const float* Wq = (const float*)d_in[3];
    const float* Wk = (const float*)d_in[4];
    const float* Wv = (const float*)d_in[5];
    const float* Wo = (const float*)d_in[6];
    const float* bq = (const float*)d_in[7];
    const float* bk = (const float*)d_in[8];
    const float* bv = (const float*)d_in[9];
    const float* bo = (const float*)d_in[10];
    const float* gamma = (const float*)d_in[11];
    const float* beta  = (const float*)d_in[12];
    float* out = (float*)d_out;

    float *x, *proj;
    cudaGetSymbolAddress((void**)&x,    g_x);
    cudaGetSymbolAddress((void**)&proj, g_proj);
    __half *xh, *xl, *ath, *atl, *vih, *vil, *wh;
    __half *qh, *kh, *kl, *vh, *vl;
    cudaGetSymbolAddress((void**)&xh, g_xh);   cudaGetSymbolAddress((void**)&xl, g_xl);
    cudaGetSymbolAddress((void**)&qh, g_qh);
    cudaGetSymbolAddress((void**)&kh, g_kh);   cudaGetSymbolAddress((void**)&kl, g_kl);
    cudaGetSymbolAddress((void**)&vh, g_vh);   cudaGetSymbolAddress((void**)&vl, g_vl);
    cudaGetSymbolAddress((void**)&ath, g_ath); cudaGetSymbolAddress((void**)&atl, g_atl);
    cudaGetSymbolAddress((void**)&vih, g_vih); cudaGetSymbolAddress((void**)&vil, g_vil);
    cudaGetSymbolAddress((void**)&wh, g_wh);

    cudaFuncSetAttribute(gemm_mma<0>, cudaFuncAttributeMaxDynamicSharedMemorySize, 2 * GSTAGE);
    cudaFuncSetAttribute(gemm_mma<2>, cudaFuncAttributeMaxDynamicSharedMemorySize, 2 * GSTAGE);
    cudaFuncSetAttribute(gemm_mma<3>, cudaFuncAttributeMaxDynamicSharedMemorySize, 2 * GSTAGE);
    cudaFuncSetAttribute(attn_mma, cudaFuncAttributeMaxDynamicSharedMemorySize, SMEM_ATTN);

    // fused setup: mask pack + activation splits + weight split/transpose
    setup_fused<<<SETUP_GRID, 256>>>(mask, query, value, Wq, Wk, Wv, Wo,
                                     xh, xl, vih, vil, wh);

    // mega K/V projection: all layers, one launch
    dim3 megagrid(16 * L_, 64);     // 4096 CTAs, 2/SM
    gemm_mma<3><<<megagrid, 256, 2*GSTAGE>>>(vih, vil, wh, bk, bv, nullptr,
                                             kh, kl, vh, vl);

    dim3 qgrid(8, 64);              // 512 CTAs, 2/SM
    dim3 agrid(S_/128, H_, B_);     // 1024 CTAs, 2/SM
    const size_t kvstride = (size_t)M_ * E_;
    for (int l = 0; l < L_; l++) {
        size_t w0 = ((size_t)(l*4 + 0)) << 20;
        size_t w3 = ((size_t)(l*4 + 3)) << 20;
        gemm_mma<2><<<qgrid, 256, 2*GSTAGE>>>(xh, xl, wh + w0,
                                              bq + l*E_, nullptr, nullptr,
                                              qh, nullptr, nullptr, nullptr);
        attn_mma<<<agrid, 256, SMEM_ATTN>>>(qh,
                                            kh + l*kvstride, kl + l*kvstride,
                                            vh + l*kvstride, vl + l*kvstride,
                                            ath, atl);
        gemm_mma<0><<<qgrid, 256, 2*GSTAGE>>>(ath, atl, wh + w3,
                                              bo + l*E_, nullptr, proj,
                                              nullptr, nullptr, nullptr, nullptr);
        add_ln_kernel<<<M_/2, 256>>>(proj, (l == 0) ? query : x,
                                     gamma + l*E_, beta + l*E_,
                                     (l == L_-1) ? out : x, xh, xl);
    }
}